// round 9
// baseline (speedup 1.0000x reference)
#include <cuda_runtime.h>
#include <cuda_bf16.h>
#include <cstdint>
#include <math.h>

#define CB 4
#define CS 2048
#define CD 512
#define CH 8
#define CDK 64
#define CM (CB*CS)      // 8192
#define CBH (CB*CH)     // 32
#define CDP (CD/2)      // 256 pairs per row
#define CSP (CS/2)      // 1024 pairs per row

// ---------------- scratch (device globals: allocation-free) ----------------
static __device__ float g_xq[CM*CD];
static __device__ float g_xk[CM*CD];
static __device__ float g_v[CM*CD];
static __device__ float g_gate[CM*CD];
static __device__ float g_ao[CM*CD];
static __device__ uint32_t g_qh[CM*CDP], g_ql[CM*CDP];   // q split bf16 pairs (pre-scaled 1/8)
static __device__ uint32_t g_kh[CM*CDP], g_kl[CM*CDP];   // k split
static __device__ uint32_t g_ph[(size_t)CBH*CS*CSP];     // exp(2x) split pairs (hi)
static __device__ uint32_t g_pl[(size_t)CBH*CS*CSP];     // (lo)
static __device__ uint32_t g_vth[CBH*CDK*CSP], g_vtl[CBH*CDK*CSP]; // V^T * ci split
static __device__ float g_rpart[(size_t)CBH*CS*64];
static __device__ float g_cpart[(size_t)CBH*CS*32];
static __device__ float g_rsum[CBH*CS];
static __device__ float g_csum[CBH*CS];

// ---------------- helpers ----------------
__device__ __forceinline__ uint32_t s2u(const void* p) {
    return (uint32_t)__cvta_generic_to_shared(p);
}
__device__ __forceinline__ void split2(float x0, float x1, uint32_t &hi, uint32_t &lo) {
    __nv_bfloat16 h0 = __float2bfloat16_rn(x0);
    __nv_bfloat16 h1 = __float2bfloat16_rn(x1);
    float r0 = x0 - __bfloat162float(h0);
    float r1 = x1 - __bfloat162float(h1);
    __nv_bfloat16 l0 = __float2bfloat16_rn(r0);
    __nv_bfloat16 l1 = __float2bfloat16_rn(r1);
    hi = (uint32_t)__bfloat16_as_ushort(h0) | ((uint32_t)__bfloat16_as_ushort(h1) << 16);
    lo = (uint32_t)__bfloat16_as_ushort(l0) | ((uint32_t)__bfloat16_as_ushort(l1) << 16);
}
__device__ __forceinline__ void mma16(float &c0, float &c1, float &c2, float &c3,
                                      uint32_t a0, uint32_t a1, uint32_t a2, uint32_t a3,
                                      uint32_t b0, uint32_t b1) {
    asm("mma.sync.aligned.m16n8k16.row.col.f32.bf16.bf16.f32 "
        "{%0,%1,%2,%3}, {%4,%5,%6,%7}, {%8,%9}, {%0,%1,%2,%3};"
        : "+f"(c0), "+f"(c1), "+f"(c2), "+f"(c3)
        : "r"(a0), "r"(a1), "r"(a2), "r"(a3), "r"(b0), "r"(b1));
}
__device__ __forceinline__ void ldsm4(uint32_t &r0, uint32_t &r1, uint32_t &r2, uint32_t &r3,
                                      uint32_t addr) {
    asm volatile("ldmatrix.sync.aligned.m8n8.x4.shared.b16 {%0,%1,%2,%3}, [%4];"
                 : "=r"(r0), "=r"(r1), "=r"(r2), "=r"(r3) : "r"(addr));
}
#define RS 12   // SMEM row stride in uint32 (48B, conflict-free)

__device__ __forceinline__ float fast_exp(float x) {
    x = fmaxf(x, -80.0f);
    float t  = x * 1.4426950408889634f;
    float fi = floorf(t);
    float f  = t - fi;
    float p  = 1.53533e-4f;
    p = fmaf(p, f, 1.33989e-3f);
    p = fmaf(p, f, 9.61844e-3f);
    p = fmaf(p, f, 5.55033e-2f);
    p = fmaf(p, f, 2.40226e-1f);
    p = fmaf(p, f, 6.93147e-1f);
    p = fmaf(p, f, 1.0f);
    return __int_as_float(((int)fi + 127) << 23) * p;
}

// ---------------- LayerNorm ----------------
__global__ __launch_bounds__(256)
void ln_kernel(const float* __restrict__ xq, const float* __restrict__ xk,
               const float* __restrict__ gamma, const float* __restrict__ beta)
{
    int row = blockIdx.x;
    const float* x; float* o;
    if (row < CM) { x = xq + (size_t)row*CD;       o = g_xq + (size_t)row*CD; }
    else          { x = xk + (size_t)(row-CM)*CD;  o = g_xk + (size_t)(row-CM)*CD; }
    int t = threadIdx.x;
    float2 v2 = ((const float2*)x)[t];
    float s  = v2.x + v2.y;
    float ss = v2.x*v2.x + v2.y*v2.y;
    #pragma unroll
    for (int off = 16; off; off >>= 1) {
        s  += __shfl_xor_sync(0xffffffffu, s,  off);
        ss += __shfl_xor_sync(0xffffffffu, ss, off);
    }
    __shared__ float sh_s[8], sh_ss[8];
    __shared__ float s_mean, s_rstd;
    int wid = t >> 5, lid = t & 31;
    if (lid == 0) { sh_s[wid] = s; sh_ss[wid] = ss; }
    __syncthreads();
    if (t < 32) {
        float a = (t < 8) ? sh_s[t]  : 0.f;
        float b = (t < 8) ? sh_ss[t] : 0.f;
        #pragma unroll
        for (int off = 4; off; off >>= 1) {
            a += __shfl_xor_sync(0xffffffffu, a, off);
            b += __shfl_xor_sync(0xffffffffu, b, off);
        }
        if (t == 0) {
            float mean = a * (1.0f/CD);
            float var  = b * (1.0f/CD) - mean*mean;
            s_mean = mean;
            s_rstd = rsqrtf(var + 1e-6f);
        }
    }
    __syncthreads();
    float mean = s_mean, rstd = s_rstd;
    float2 g2 = ((const float2*)gamma)[t];
    float2 b2 = ((const float2*)beta)[t];
    float2 o2;
    o2.x = (v2.x - mean) * rstd * g2.x + b2.x;
    o2.y = (v2.y - mean) * rstd * g2.y + b2.y;
    ((float2*)o)[t] = o2;
}

// ---------------- merged projections: z = 0 q / 1 k / 2 v / 3 gate ----------
__global__ __launch_bounds__(256, 2)
void proj_all(const float* __restrict__ Wq, const float* __restrict__ Wk,
              const float* __restrict__ Wv, const float* __restrict__ Wg,
              const float* __restrict__ bg)
{
    __shared__ uint32_t Ah[2][128][RS], Al[2][128][RS];
    __shared__ uint32_t Bh[2][128][RS], Bl[2][128][RS];
    int mode = blockIdx.z;
    const float* A = (mode == 0 || mode == 3) ? g_xq : g_xk;
    const float* B = (mode == 0) ? Wq : (mode == 1) ? Wk : (mode == 2) ? Wv : Wg;
    float scale = (mode == 0) ? 0.125f : 1.0f;

    int tid = threadIdx.x, wid = tid >> 5, lane = tid & 31;
    int wm = wid & 1, wn = wid >> 1;
    int m0 = blockIdx.y * 128, n0 = blockIdx.x * 128;
    const float* Ag = A + (size_t)m0 * CD;
    const float* Bg = B + (size_t)n0 * CD;
    int lr = tid >> 2, lc = (tid & 3) * 4, kp = (tid & 3) * 2;
    int qr = lane >> 2, qc = lane & 3;

    const uint32_t BUF = 128*RS*4;
    uint32_t aAh = s2u(Ah), aAl = s2u(Al), aBh = s2u(Bh), aBl = s2u(Bl);
    uint32_t offA = (uint32_t)(lane & 15) * (RS*4) + (uint32_t)((lane >> 4) & 1) * 16;
    uint32_t offB = (uint32_t)((lane & 7) + ((lane >> 4) & 1) * 8) * (RS*4)
                  + (uint32_t)((lane >> 3) & 1) * 16;

    float acc[4][4][4];
    #pragma unroll
    for (int i = 0; i < 4; i++)
        #pragma unroll
        for (int j = 0; j < 4; j++)
            #pragma unroll
            for (int e = 0; e < 4; e++) acc[i][j][e] = 0.f;

    float4 pa0 = *(const float4*)(Ag + (size_t)lr*CD + lc);
    float4 pa1 = *(const float4*)(Ag + (size_t)(lr+64)*CD + lc);
    float4 pb0 = *(const float4*)(Bg + (size_t)lr*CD + lc);
    float4 pb1 = *(const float4*)(Bg + (size_t)(lr+64)*CD + lc);
    const int NC = CD / 16;

    {
        uint2 h, l;
        split2(pa0.x, pa0.y, h.x, l.x); split2(pa0.z, pa0.w, h.y, l.y);
        *(uint2*)&Ah[0][lr][kp] = h; *(uint2*)&Al[0][lr][kp] = l;
        split2(pa1.x, pa1.y, h.x, l.x); split2(pa1.z, pa1.w, h.y, l.y);
        *(uint2*)&Ah[0][lr+64][kp] = h; *(uint2*)&Al[0][lr+64][kp] = l;
        split2(pb0.x, pb0.y, h.x, l.x); split2(pb0.z, pb0.w, h.y, l.y);
        *(uint2*)&Bh[0][lr][kp] = h; *(uint2*)&Bl[0][lr][kp] = l;
        split2(pb1.x, pb1.y, h.x, l.x); split2(pb1.z, pb1.w, h.y, l.y);
        *(uint2*)&Bh[0][lr+64][kp] = h; *(uint2*)&Bl[0][lr+64][kp] = l;
    }
    {
        int k0 = 16 + lc;
        pa0 = *(const float4*)(Ag + (size_t)lr*CD + k0);
        pa1 = *(const float4*)(Ag + (size_t)(lr+64)*CD + k0);
        pb0 = *(const float4*)(Bg + (size_t)lr*CD + k0);
        pb1 = *(const float4*)(Bg + (size_t)(lr+64)*CD + k0);
    }
    __syncthreads();

    for (int c = 0; c < NC; c++) {
        uint32_t cb = (uint32_t)(c & 1) * BUF;
        uint32_t bh[4][2], bl[4][2];
        #pragma unroll
        for (int ntp = 0; ntp < 2; ntp++) {
            uint32_t nbase = (uint32_t)(wn*32 + ntp*16) * (RS*4);
            ldsm4(bh[2*ntp][0], bh[2*ntp][1], bh[2*ntp+1][0], bh[2*ntp+1][1], aBh + cb + nbase + offB);
            ldsm4(bl[2*ntp][0], bl[2*ntp][1], bl[2*ntp+1][0], bl[2*ntp+1][1], aBl + cb + nbase + offB);
        }
        #pragma unroll
        for (int mt = 0; mt < 4; mt++) {
            uint32_t rbase = (uint32_t)(wm*64 + mt*16) * (RS*4);
            uint32_t ah0, ah1, ah2, ah3, al0, al1, al2, al3;
            ldsm4(ah0, ah1, ah2, ah3, aAh + cb + rbase + offA);
            ldsm4(al0, al1, al2, al3, aAl + cb + rbase + offA);
            #pragma unroll
            for (int nt = 0; nt < 4; nt++) {
                mma16(acc[mt][nt][0], acc[mt][nt][1], acc[mt][nt][2], acc[mt][nt][3],
                      ah0, ah1, ah2, ah3, bh[nt][0], bh[nt][1]);
                mma16(acc[mt][nt][0], acc[mt][nt][1], acc[mt][nt][2], acc[mt][nt][3],
                      ah0, ah1, ah2, ah3, bl[nt][0], bl[nt][1]);
                mma16(acc[mt][nt][0], acc[mt][nt][1], acc[mt][nt][2], acc[mt][nt][3],
                      al0, al1, al2, al3, bh[nt][0], bh[nt][1]);
            }
        }
        if (c + 1 < NC) {
            int ni = (c & 1) ^ 1;
            uint2 h, l;
            split2(pa0.x, pa0.y, h.x, l.x); split2(pa0.z, pa0.w, h.y, l.y);
            *(uint2*)&Ah[ni][lr][kp] = h; *(uint2*)&Al[ni][lr][kp] = l;
            split2(pa1.x, pa1.y, h.x, l.x); split2(pa1.z, pa1.w, h.y, l.y);
            *(uint2*)&Ah[ni][lr+64][kp] = h; *(uint2*)&Al[ni][lr+64][kp] = l;
            split2(pb0.x, pb0.y, h.x, l.x); split2(pb0.z, pb0.w, h.y, l.y);
            *(uint2*)&Bh[ni][lr][kp] = h; *(uint2*)&Bl[ni][lr][kp] = l;
            split2(pb1.x, pb1.y, h.x, l.x); split2(pb1.z, pb1.w, h.y, l.y);
            *(uint2*)&Bh[ni][lr+64][kp] = h; *(uint2*)&Bl[ni][lr+64][kp] = l;
            if (c + 2 < NC) {
                int k0 = (c+2)*16 + lc;
                pa0 = *(const float4*)(Ag + (size_t)lr*CD + k0);
                pa1 = *(const float4*)(Ag + (size_t)(lr+64)*CD + k0);
                pb0 = *(const float4*)(Bg + (size_t)lr*CD + k0);
                pb1 = *(const float4*)(Bg + (size_t)(lr+64)*CD + k0);
            }
        }
        __syncthreads();
    }

    // epilogue
    uint32_t* Oh = (mode == 0) ? g_qh : g_kh;
    uint32_t* Ol = (mode == 0) ? g_ql : g_kl;
    float* Of = (mode == 2) ? g_v : g_gate;
    #pragma unroll
    for (int mt = 0; mt < 4; mt++) {
        int r = m0 + wm*64 + mt*16 + qr;
        #pragma unroll
        for (int nt = 0; nt < 4; nt++) {
            int col = n0 + wn*32 + nt*8 + qc*2;
            float o0 = acc[mt][nt][0]*scale, o1 = acc[mt][nt][1]*scale;
            float o2 = acc[mt][nt][2]*scale, o3 = acc[mt][nt][3]*scale;
            if (mode <= 1) {
                uint32_t hi, lo;
                int colp = col >> 1;
                split2(o0, o1, hi, lo);
                Oh[(size_t)r*CDP + colp] = hi; Ol[(size_t)r*CDP + colp] = lo;
                split2(o2, o3, hi, lo);
                Oh[(size_t)(r+8)*CDP + colp] = hi; Ol[(size_t)(r+8)*CDP + colp] = lo;
            } else {
                if (mode == 3) {
                    float b0 = bg[col], b1 = bg[col+1];
                    o0 = 1.0f/(1.0f + __expf(-(o0+b0)));
                    o1 = 1.0f/(1.0f + __expf(-(o1+b1)));
                    o2 = 1.0f/(1.0f + __expf(-(o2+b0)));
                    o3 = 1.0f/(1.0f + __expf(-(o3+b1)));
                }
                *(float2*)(Of + (size_t)r*CD + col)     = make_float2(o0, o1);
                *(float2*)(Of + (size_t)(r+8)*CD + col) = make_float2(o2, o3);
            }
        }
    }
}

// ---------------- scores + stats: reads pre-split q,k; writes exp(2x) pairs -
__global__ __launch_bounds__(256, 2)
void scores_stats()
{
    __shared__ uint32_t Ah[2][128][RS], Al[2][128][RS];
    __shared__ uint32_t Bh[2][128][RS], Bl[2][128][RS];
    int z = blockIdx.z, b = z >> 3, h = z & 7;
    int m0 = blockIdx.y * 128, n0 = blockIdx.x * 128;
    int tid = threadIdx.x, wid = tid >> 5, lane = tid & 31;
    int wm = wid & 1, wn = wid >> 1;
    int lr = tid >> 2, kp = (tid & 3) * 2;
    int qr = lane >> 2, qc = lane & 3;

    const uint32_t* Aqh = g_qh + (size_t)(b*CS + m0)*CDP + h*32;
    const uint32_t* Aql = g_ql + (size_t)(b*CS + m0)*CDP + h*32;
    const uint32_t* Bkh = g_kh + (size_t)(b*CS + n0)*CDP + h*32;
    const uint32_t* Bkl = g_kl + (size_t)(b*CS + n0)*CDP + h*32;

    const uint32_t BUF = 128*RS*4;
    uint32_t aAh = s2u(Ah), aAl = s2u(Al), aBh = s2u(Bh), aBl = s2u(Bl);
    uint32_t offA = (uint32_t)(lane & 15) * (RS*4) + (uint32_t)((lane >> 4) & 1) * 16;
    uint32_t offB = (uint32_t)((lane & 7) + ((lane >> 4) & 1) * 8) * (RS*4)
                  + (uint32_t)((lane >> 3) & 1) * 16;

    float acc[4][4][4];
    #pragma unroll
    for (int i = 0; i < 4; i++)
        #pragma unroll
        for (int j = 0; j < 4; j++)
            #pragma unroll
            for (int e = 0; e < 4; e++) acc[i][j][e] = 0.f;

    uint2 rqh0, rqh1, rql0, rql1, rkh0, rkh1, rkl0, rkl1;
    #define SLOAD(c) do { \
        size_t o0_ = (size_t)lr*CDP + (c)*8 + kp; \
        size_t o1_ = (size_t)(lr+64)*CDP + (c)*8 + kp; \
        rqh0 = *(const uint2*)(Aqh + o0_); rqh1 = *(const uint2*)(Aqh + o1_); \
        rql0 = *(const uint2*)(Aql + o0_); rql1 = *(const uint2*)(Aql + o1_); \
        rkh0 = *(const uint2*)(Bkh + o0_); rkh1 = *(const uint2*)(Bkh + o1_); \
        rkl0 = *(const uint2*)(Bkl + o0_); rkl1 = *(const uint2*)(Bkl + o1_); \
    } while (0)
    #define SSTAGE(bi) do { \
        *(uint2*)&Ah[bi][lr][kp] = rqh0; *(uint2*)&Ah[bi][lr+64][kp] = rqh1; \
        *(uint2*)&Al[bi][lr][kp] = rql0; *(uint2*)&Al[bi][lr+64][kp] = rql1; \
        *(uint2*)&Bh[bi][lr][kp] = rkh0; *(uint2*)&Bh[bi][lr+64][kp] = rkh1; \
        *(uint2*)&Bl[bi][lr][kp] = rkl0; *(uint2*)&Bl[bi][lr+64][kp] = rkl1; \
    } while (0)

    const int NC = CDK / 16;   // 4
    SLOAD(0); SSTAGE(0); SLOAD(1);
    __syncthreads();

    for (int c = 0; c < NC; c++) {
        uint32_t cb = (uint32_t)(c & 1) * BUF;
        uint32_t bh[4][2], bl[4][2];
        #pragma unroll
        for (int ntp = 0; ntp < 2; ntp++) {
            uint32_t nbase = (uint32_t)(wn*32 + ntp*16) * (RS*4);
            ldsm4(bh[2*ntp][0], bh[2*ntp][1], bh[2*ntp+1][0], bh[2*ntp+1][1], aBh + cb + nbase + offB);
            ldsm4(bl[2*ntp][0], bl[2*ntp][1], bl[2*ntp+1][0], bl[2*ntp+1][1], aBl + cb + nbase + offB);
        }
        #pragma unroll
        for (int mt = 0; mt < 4; mt++) {
            uint32_t rbase = (uint32_t)(wm*64 + mt*16) * (RS*4);
            uint32_t ah0, ah1, ah2, ah3, al0, al1, al2, al3;
            ldsm4(ah0, ah1, ah2, ah3, aAh + cb + rbase + offA);
            ldsm4(al0, al1, al2, al3, aAl + cb + rbase + offA);
            #pragma unroll
            for (int nt = 0; nt < 4; nt++) {
                mma16(acc[mt][nt][0], acc[mt][nt][1], acc[mt][nt][2], acc[mt][nt][3],
                      ah0, ah1, ah2, ah3, bh[nt][0], bh[nt][1]);
                mma16(acc[mt][nt][0], acc[mt][nt][1], acc[mt][nt][2], acc[mt][nt][3],
                      ah0, ah1, ah2, ah3, bl[nt][0], bl[nt][1]);
                mma16(acc[mt][nt][0], acc[mt][nt][1], acc[mt][nt][2], acc[mt][nt][3],
                      al0, al1, al2, al3, bh[nt][0], bh[nt][1]);
            }
        }
        if (c + 1 < NC) {
            SSTAGE((c+1) & 1);
            if (c + 2 < NC) SLOAD(c+2);
        }
        __syncthreads();
    }

    // epilogue: ex = exp(x); stats partials; store split(ex^2) pairs
    float csl[4][2];
    #pragma unroll
    for (int nt = 0; nt < 4; nt++) { csl[nt][0] = 0.f; csl[nt][1] = 0.f; }
    #pragma unroll
    for (int mt = 0; mt < 4; mt++) {
        float ex[4][4];
        #pragma unroll
        for (int nt = 0; nt < 4; nt++)
            #pragma unroll
            for (int e = 0; e < 4; e++) ex[nt][e] = fast_exp(acc[mt][nt][e]);
        float r0 = 0.f, r1 = 0.f;
        #pragma unroll
        for (int nt = 0; nt < 4; nt++) {
            r0 += ex[nt][0] + ex[nt][1];
            r1 += ex[nt][2] + ex[nt][3];
            csl[nt][0] += ex[nt][0] + ex[nt][2];
            csl[nt][1] += ex[nt][1] + ex[nt][3];
        }
        r0 += __shfl_xor_sync(0xffffffffu, r0, 1);
        r0 += __shfl_xor_sync(0xffffffffu, r0, 2);
        r1 += __shfl_xor_sync(0xffffffffu, r1, 1);
        r1 += __shfl_xor_sync(0xffffffffu, r1, 2);
        int row0 = m0 + wm*64 + mt*16 + qr;
        if (qc == 0) {
            int rslot = blockIdx.x * 4 + wn;
            g_rpart[((size_t)(z*CS + row0) << 6) + rslot]     = r0;
            g_rpart[((size_t)(z*CS + row0 + 8) << 6) + rslot] = r1;
        }
        #pragma unroll
        for (int nt = 0; nt < 4; nt++) {
            int colp = (n0 >> 1) + wn*16 + nt*4 + qc;
            uint32_t hi, lo;
            split2(ex[nt][0]*ex[nt][0], ex[nt][1]*ex[nt][1], hi, lo);
            g_ph[(size_t)(z*CS + row0)*CSP + colp] = hi;
            g_pl[(size_t)(z*CS + row0)*CSP + colp] = lo;
            split2(ex[nt][2]*ex[nt][2], ex[nt][3]*ex[nt][3], hi, lo);
            g_ph[(size_t)(z*CS + row0 + 8)*CSP + colp] = hi;
            g_pl[(size_t)(z*CS + row0 + 8)*CSP + colp] = lo;
        }
    }
    #pragma unroll
    for (int nt = 0; nt < 4; nt++) {
        #pragma unroll
        for (int j = 0; j < 2; j++) {
            float v = csl[nt][j];
            v += __shfl_xor_sync(0xffffffffu, v, 4);
            v += __shfl_xor_sync(0xffffffffu, v, 8);
            v += __shfl_xor_sync(0xffffffffu, v, 16);
            if (qr == 0) {
                int cslot = blockIdx.y * 2 + wm;
                int col = n0 + wn*32 + nt*8 + qc*2 + j;
                g_cpart[((size_t)(z*CS + col) << 5) + cslot] = v;
            }
        }
    }
}

// ---------------- finalize: reduce partials -> reciprocals ------------------
__global__ __launch_bounds__(256)
void finalize_kernel()
{
    int i = blockIdx.x * 256 + threadIdx.x;
    if (i < CBH*CS) {
        const float4* p = (const float4*)(g_rpart + ((size_t)i << 6));
        float s = 0.f;
        #pragma unroll
        for (int j = 0; j < 16; j++) {
            float4 v = p[j];
            s += v.x + v.y + v.z + v.w;
        }
        g_rsum[i] = 1.0f / s;
    } else {
        i -= CBH*CS;
        const float4* p = (const float4*)(g_cpart + ((size_t)i << 5));
        float s = 0.f;
        #pragma unroll
        for (int j = 0; j < 8; j++) {
            float4 v = p[j];
            s += v.x + v.y + v.z + v.w;
        }
        g_csum[i] = 1.0f / s;
    }
}

// ---------------- V transpose with ci folded, split output ------------------
__global__ __launch_bounds__(256)
void vtrans_ci()
{
    __shared__ float tile[64][65];
    int z = blockIdx.y, b = z >> 3, h = z & 7;
    int t0 = blockIdx.x * 64;
    const float* src = g_v + (size_t)b*CS*CD + h*CDK;
    int tid = threadIdx.x;
    #pragma unroll
    for (int i = 0; i < 16; i++) {
        int idx = tid + i*256;
        int tr = idx >> 6, d = idx & 63;
        tile[tr][d] = src[(size_t)(t0 + tr)*CD + d] * g_csum[z*CS + t0 + tr];
    }
    __syncthreads();
    #pragma unroll
    for (int i = 0; i < 8; i++) {
        int idx = tid + i*256;
        int d = idx >> 5, tp = idx & 31;
        uint32_t hi, lo;
        split2(tile[2*tp][d], tile[2*tp+1][d], hi, lo);
        size_t o = ((size_t)z*CDK + d)*CSP + (t0 >> 1) + tp;
        g_vth[o] = hi; g_vtl[o] = lo;
    }
}

// ---------------- PV: pure pre-split GEMM, epilogue ri*gate -----------------
__global__ __launch_bounds__(256)
void pv_kernel()
{
    __shared__ uint32_t Ph[2][128][RS], Pl[2][128][RS];
    __shared__ uint32_t Vh[2][64][RS],  Vl[2][64][RS];
    int z = blockIdx.y, b = z >> 3, h = z & 7;
    int s0 = blockIdx.x * 128;
    int tid = threadIdx.x, wid = tid >> 5, lane = tid & 31;
    int wm = wid & 3, wn = wid >> 2;
    int qr = lane >> 2, qc = lane & 3;

    int pr = tid >> 1;                 // P row 0..127
    int pp = (tid & 1) * 4;            // pair base 0/4
    int vr = tid >> 2;                 // V^T row (dk) 0..63
    int vp = (tid & 3) * 2;            // pair base 0,2,4,6
    const uint32_t* aph = g_ph + (size_t)(z*CS + s0 + pr)*CSP;
    const uint32_t* apl = g_pl + (size_t)(z*CS + s0 + pr)*CSP;
    const uint32_t* avh = g_vth + ((size_t)z*CDK + vr)*CSP;
    const uint32_t* avl = g_vtl + ((size_t)z*CDK + vr)*CSP;

    const uint32_t BUFP = 128*RS*4, BUFV = 64*RS*4;
    uint32_t aPh = s2u(Ph), aPl = s2u(Pl), aVh = s2u(Vh), aVl = s2u(Vl);
    uint32_t offA = (uint32_t)(lane & 15) * (RS*4) + (uint32_t)((lane >> 4) & 1) * 16;
    uint32_t offB = (uint32_t)((lane & 7) + ((lane >> 4) & 1) * 8) * (RS*4)
                  + (uint32_t)((lane >> 3) & 1) * 16;

    float acc[2][4][4];
    #pragma unroll
    for (int i = 0; i < 2; i++)
        #pragma unroll
        for (int j = 0; j < 4; j++)
            #pragma unroll
            for (int e = 0; e < 4; e++) acc[i][j][e] = 0.f;

    uint4 rph, rpl; uint2 rvh, rvl;
    #define PLOAD(c) do { \
        rph = *(const uint4*)(aph + (c)*8 + pp); \
        rpl = *(const uint4*)(apl + (c)*8 + pp); \
        rvh = *(const uint2*)(avh + (c)*8 + vp); \
        rvl = *(const uint2*)(avl + (c)*8 + vp); \
    } while (0)
    #define PSTAGE(bi) do { \
        *(uint4*)&Ph[bi][pr][pp] = rph; \
        *(uint4*)&Pl[bi][pr][pp] = rpl; \
        *(uint2*)&Vh[bi][vr][vp] = rvh; \
        *(uint2*)&Vl[bi][vr][vp] = rvl; \
    } while (0)

    const int NC = CS / 16;            // 128 chunks
    PLOAD(0); PSTAGE(0); PLOAD(1);
    __syncthreads();

    for (int c = 0; c < NC; c++) {
        uint32_t cbP = (uint32_t)(c & 1) * BUFP;
        uint32_t cbV = (uint32_t)(c & 1) * BUFV;
        uint32_t bh[4][2], bl[4][2];
        #pragma unroll
        for (int ntp = 0; ntp < 2; ntp++) {
            uint32_t nbase = (uint32_t)(wn*32 + ntp*16) * (RS*4);
            ldsm4(bh[2*ntp][0], bh[2*ntp][1], bh[2*ntp+1][0], bh[2*ntp+1][1], aVh + cbV + nbase + offB);
            ldsm4(bl[2*ntp][0], bl[2*ntp][1], bl[2*ntp+1][0], bl[2*ntp+1][1], aVl + cbV + nbase + offB);
        }
        #pragma unroll
        for (int mt = 0; mt < 2; mt++) {
            uint32_t rbase = (uint32_t)(wm*32 + mt*16) * (RS*4);
            uint32_t ah0, ah1, ah2, ah3, al0, al1, al2, al3;
            ldsm4(ah0, ah1, ah2, ah3, aPh + cbP + rbase + offA);
            ldsm4(al0, al1, al2, al3, aPl + cbP + rbase + offA);
            #pragma unroll
            for (int nt = 0; nt < 4; nt++) {
                mma16(acc[mt][nt][0], acc[mt][nt][1], acc[mt][nt][2], acc[mt][nt][3],
                      ah0, ah1, ah2, ah3, bh[nt][0], bh[nt][1]);
                mma16(acc[mt][nt][0], acc[mt][nt][1], acc[mt][nt][2], acc[mt][nt][3],
                      ah0, ah1, ah2, ah3, bl[nt][0], bl[nt][1]);
                mma16(acc[mt][nt][0], acc[mt][nt][1], acc[mt][nt][2], acc[mt][nt][3],
                      al0, al1, al2, al3, bh[nt][0], bh[nt][1]);
            }
        }
        if (c + 1 < NC) {
            PSTAGE((c+1) & 1);
            if (c + 2 < NC) PLOAD(c+2);
        }
        __syncthreads();
    }
    // epilogue: * rsum_inv, * gate -> g_ao
    #pragma unroll
    for (int mt = 0; mt < 2; mt++) {
        #pragma unroll
        for (int half = 0; half < 2; half++) {
            int srow = s0 + wm*32 + mt*16 + qr + half*8;
            float ri = g_rsum[(size_t)z*CS + srow];
            const float* grow = g_gate + ((size_t)b*CS + srow)*CD + h*CDK;
            float* orow       = g_ao   + ((size_t)b*CS + srow)*CD + h*CDK;
            #pragma unroll
            for (int nt = 0; nt < 4; nt++) {
                int col = wn*32 + nt*8 + qc*2;
                float o0 = acc[mt][nt][half*2+0] * ri;
                float o1 = acc[mt][nt][half*2+1] * ri;
                float2 gg = *(const float2*)(grow + col);
                *(float2*)(orow + col) = make_float2(o0*gg.x, o1*gg.y);
            }
        }
    }
}

// ---------------- output projection: A=g_ao (fp32), bias, -> d_out ----------
__global__ __launch_bounds__(256, 2)
void out_gemm(const float* __restrict__ Wo, const float* __restrict__ bo,
              float* __restrict__ C)
{
    __shared__ uint32_t Ah[2][128][RS], Al[2][128][RS];
    __shared__ uint32_t Bh[2][128][RS], Bl[2][128][RS];
    int tid = threadIdx.x, wid = tid >> 5, lane = tid & 31;
    int wm = wid & 1, wn = wid >> 1;
    int m0 = blockIdx.y * 128, n0 = blockIdx.x * 128;
    const float* Ag = g_ao + (size_t)m0 * CD;
    const float* Bg = Wo + (size_t)n0 * CD;
    int lr = tid >> 2, lc = (tid & 3) * 4, kp = (tid & 3) * 2;
    int qr = lane >> 2, qc = lane & 3;

    const uint32_t BUF = 128*RS*4;
    uint32_t aAh = s2u(Ah), aAl = s2u(Al), aBh = s2u(Bh), aBl = s2u(Bl);
    uint32_t offA = (uint32_t)(lane & 15) * (RS*4) + (uint32_t)((lane >> 4) & 1) * 16;
    uint32_t offB = (uint32_t)((lane & 7) + ((lane >> 4) & 1) * 8) * (RS*4)
                  + (uint32_t)((lane >> 3) & 1) * 16;

    float acc[4][4][4];
    #pragma unroll
    for (int i = 0; i < 4; i++)
        #pragma unroll
        for (int j = 0; j < 4; j++)
            #pragma unroll
            for (int e = 0; e < 4; e++) acc[i][j][e] = 0.f;

    float4 pa0 = *(const float4*)(Ag + (size_t)lr*CD + lc);
    float4 pa1 = *(const float4*)(Ag + (size_t)(lr+64)*CD + lc);
    float4 pb0 = *(const float4*)(Bg + (size_t)lr*CD + lc);
    float4 pb1 = *(const float4*)(Bg + (size_t)(lr+64)*CD + lc);
    const int NC = CD / 16;
    {
        uint2 h, l;
        split2(pa0.x, pa0.y, h.x, l.x); split2(pa0.z, pa0.w, h.y, l.y);
        *(uint2*)&Ah[0][lr][kp] = h; *(uint2*)&Al[0][lr][kp] = l;
        split2(pa1.x, pa1.y, h.x, l.x); split2(pa1.z, pa1.w, h.y, l.y);
        *(uint2*)&Ah[0][lr+64][kp] = h; *(uint2*)&Al[0][lr+64][kp] = l;
        split2(pb0.x, pb0.y, h.x, l.x); split2(pb0.z, pb0.w, h.y, l.y);
        *(uint2*)&Bh[0][lr][kp] = h; *(uint2*)&Bl[0][lr][kp] = l;
        split2(pb1.x, pb1.y, h.x, l.x); split2(pb1.z, pb1.w, h.y, l.y);
        *(uint2*)&Bh[0][lr+64][kp] = h; *(uint2*)&Bl[0][lr+64][kp] = l;
    }
    {
        int k0 = 16 + lc;
        pa0 = *(const float4*)(Ag + (size_t)lr*CD + k0);
        pa1 = *(const float4*)(Ag + (size_t)(lr+64)*CD + k0);
        pb0 = *(const float4*)(Bg + (size_t)lr*CD + k0);
        pb1 = *(const float4*)(Bg + (size_t)(lr+64)*CD + k0);
    }
    __syncthreads();

    for (int c = 0; c < NC; c++) {
        uint32_t cb = (uint32_t)(c & 1) * BUF;
        uint32_t bh[4][2], bl[4][2];
        #pragma unroll
        for (int ntp = 0; ntp < 2; ntp++) {
            uint32_t nbase = (uint32_t)(wn*32 + ntp*16) * (RS*4);
            ldsm4(bh[2*ntp][0], bh[2*ntp][1], bh[2*ntp+1][0], bh[2*ntp+1][1], aBh + cb + nbase + offB);
            ldsm4(bl[2*ntp][0], bl[2*ntp][1], bl[2*ntp+1][0], bl[2*ntp+1][1], aBl + cb + nbase + offB);
        }
        #pragma unroll
        for (int mt = 0; mt < 4; mt++) {
            uint32_t rbase = (uint32_t)(wm*64 + mt*16) * (RS*4);
            uint32_t ah0, ah1, ah2, ah3, al0, al1, al2, al3;
            ldsm4(ah0, ah1, ah2, ah3, aAh + cb + rbase + offA);
            ldsm4(al0, al1, al2, al3, aAl + cb + rbase + offA);
            #pragma unroll
            for (int nt = 0; nt < 4; nt++) {
                mma16(acc[mt][nt][0], acc[mt][nt][1], acc[mt][nt][2], acc[mt][nt][3],
                      ah0, ah1, ah2, ah3, bh[nt][0], bh[nt][1]);
                mma16(acc[mt][nt][0], acc[mt][nt][1], acc[mt][nt][2], acc[mt][nt][3],
                      ah0, ah1, ah2, ah3, bl[nt][0], bl[nt][1]);
                mma16(acc[mt][nt][0], acc[mt][nt][1], acc[mt][nt][2], acc[mt][nt][3],
                      al0, al1, al2, al3, bh[nt][0], bh[nt][1]);
            }
        }
        if (c + 1 < NC) {
            int ni = (c & 1) ^ 1;
            uint2 h, l;
            split2(pa0.x, pa0.y, h.x, l.x); split2(pa0.z, pa0.w, h.y, l.y);
            *(uint2*)&Ah[ni][lr][kp] = h; *(uint2*)&Al[ni][lr][kp] = l;
            split2(pa1.x, pa1.y, h.x, l.x); split2(pa1.z, pa1.w, h.y, l.y);
            *(uint2*)&Ah[ni][lr+64][kp] = h; *(uint2*)&Al[ni][lr+64][kp] = l;
            split2(pb0.x, pb0.y, h.x, l.x); split2(pb0.z, pb0.w, h.y, l.y);
            *(uint2*)&Bh[ni][lr][kp] = h; *(uint2*)&Bl[ni][lr][kp] = l;
            split2(pb1.x, pb1.y, h.x, l.x); split2(pb1.z, pb1.w, h.y, l.y);
            *(uint2*)&Bh[ni][lr+64][kp] = h; *(uint2*)&Bl[ni][lr+64][kp] = l;
            if (c + 2 < NC) {
                int k0 = (c+2)*16 + lc;
                pa0 = *(const float4*)(Ag + (size_t)lr*CD + k0);
                pa1 = *(const float4*)(Ag + (size_t)(lr+64)*CD + k0);
                pb0 = *(const float4*)(Bg + (size_t)lr*CD + k0);
                pb1 = *(const float4*)(Bg + (size_t)(lr+64)*CD + k0);
            }
        }
        __syncthreads();
    }
    #pragma unroll
    for (int mt = 0; mt < 4; mt++) {
        int r = m0 + wm*64 + mt*16 + qr;
        #pragma unroll
        for (int nt = 0; nt < 4; nt++) {
            int col = n0 + wn*32 + nt*8 + qc*2;
            float b0 = bo[col], b1 = bo[col+1];
            *(float2*)(C + (size_t)r*CD + col) =
                make_float2(acc[mt][nt][0] + b0, acc[mt][nt][1] + b1);
            *(float2*)(C + (size_t)(r+8)*CD + col) =
                make_float2(acc[mt][nt][2] + b0, acc[mt][nt][3] + b1);
        }
    }
}

// ---------------- launch ----------------
extern "C" void kernel_launch(void* const* d_in, const int* in_sizes, int n_in,
                              void* d_out, int out_size)
{
    const float* x_q   = (const float*)d_in[0];
    const float* x_k   = (const float*)d_in[1];
    const float* Wq    = (const float*)d_in[2];
    const float* Wk    = (const float*)d_in[3];
    const float* Wv    = (const float*)d_in[4];
    const float* Wg    = (const float*)d_in[5];
    const float* bg    = (const float*)d_in[6];
    const float* Wo    = (const float*)d_in[7];
    const float* bo    = (const float*)d_in[8];
    const float* gamma = (const float*)d_in[9];
    const float* beta  = (const float*)d_in[10];
    float* out = (float*)d_out;

    // 1. LayerNorm
    ln_kernel<<<2*CM, 256>>>(x_q, x_k, gamma, beta);

    // 2. All projections in one launch (q,k pre-split; q pre-scaled 1/8)
    proj_all<<<dim3(CD/128, CM/128, 4), 256>>>(Wq, Wk, Wv, Wg, bg);

    // 3. Scores + stats (pure-copy staging), store exp(2x) pre-split
    scores_stats<<<dim3(CS/128, CS/128, CBH), 256>>>();

    // 4. Reduce partials -> reciprocal sums
    finalize_kernel<<<(2*CBH*CS)/256, 256>>>();

    // 5. V transpose with ci folded, pre-split
    vtrans_ci<<<dim3(CS/64, CBH), 256>>>();

    // 6. PV: pure pre-split GEMM, ri*gate fused
    pv_kernel<<<dim3(CS/128, CBH), 256>>>();

    // 7. Output projection + bias -> d_out
    out_gemm<<<dim3(CD/128, CM/128), 256>>>(Wo, bo, out);
}

// round 10
// speedup vs baseline: 1.6077x; 1.6077x over previous
#include <cuda_runtime.h>
#include <cuda_bf16.h>
#include <cstdint>
#include <math.h>

#define CB 4
#define CS 2048
#define CD 512
#define CH 8
#define CDK 64
#define CM (CB*CS)      // 8192
#define CBH (CB*CH)     // 32
#define CSP (CS/2)      // 1024 pairs per score row

// ---------------- scratch (device globals: allocation-free) ----------------
static __device__ float g_xq[CM*CD];
static __device__ float g_xk[CM*CD];
static __device__ float g_q[CM*CD];      // pre-scaled by 1/8
static __device__ float g_k[CM*CD];
static __device__ float g_v[CM*CD];
static __device__ float g_gate[CM*CD];
static __device__ float g_ao[CM*CD];
static __device__ uint2 g_p[(size_t)CBH*CS*CSP];      // split(exp(2x)) pairs, interleaved (hi,lo)
static __device__ uint2 g_vtp[CBH*CDK*CSP];           // split(V^T * ci) pairs, interleaved
static __device__ float g_rpart[(size_t)CBH*CS*64];
static __device__ float g_cpart[(size_t)CBH*CS*32];
static __device__ float g_rsum[CBH*CS];
static __device__ float g_csum[CBH*CS];

// ---------------- helpers ----------------
__device__ __forceinline__ uint32_t s2u(const void* p) {
    return (uint32_t)__cvta_generic_to_shared(p);
}
__device__ __forceinline__ void split2(float x0, float x1, uint32_t &hi, uint32_t &lo) {
    __nv_bfloat16 h0 = __float2bfloat16_rn(x0);
    __nv_bfloat16 h1 = __float2bfloat16_rn(x1);
    float r0 = x0 - __bfloat162float(h0);
    float r1 = x1 - __bfloat162float(h1);
    __nv_bfloat16 l0 = __float2bfloat16_rn(r0);
    __nv_bfloat16 l1 = __float2bfloat16_rn(r1);
    hi = (uint32_t)__bfloat16_as_ushort(h0) | ((uint32_t)__bfloat16_as_ushort(h1) << 16);
    lo = (uint32_t)__bfloat16_as_ushort(l0) | ((uint32_t)__bfloat16_as_ushort(l1) << 16);
}
__device__ __forceinline__ void mma16(float &c0, float &c1, float &c2, float &c3,
                                      uint32_t a0, uint32_t a1, uint32_t a2, uint32_t a3,
                                      uint32_t b0, uint32_t b1) {
    asm("mma.sync.aligned.m16n8k16.row.col.f32.bf16.bf16.f32 "
        "{%0,%1,%2,%3}, {%4,%5,%6,%7}, {%8,%9}, {%0,%1,%2,%3};"
        : "+f"(c0), "+f"(c1), "+f"(c2), "+f"(c3)
        : "r"(a0), "r"(a1), "r"(a2), "r"(a3), "r"(b0), "r"(b1));
}
__device__ __forceinline__ void ldsm4(uint32_t &r0, uint32_t &r1, uint32_t &r2, uint32_t &r3,
                                      uint32_t addr) {
    asm volatile("ldmatrix.sync.aligned.m8n8.x4.shared.b16 {%0,%1,%2,%3}, [%4];"
                 : "=r"(r0), "=r"(r1), "=r"(r2), "=r"(r3) : "r"(addr));
}
#define RS 12   // SMEM row stride in uint32 (48B, conflict-free)

__device__ __forceinline__ float fast_exp(float x) {
    x = fmaxf(x, -80.0f);
    float t  = x * 1.4426950408889634f;
    float fi = floorf(t);
    float f  = t - fi;
    float p  = 1.53533e-4f;
    p = fmaf(p, f, 1.33989e-3f);
    p = fmaf(p, f, 9.61844e-3f);
    p = fmaf(p, f, 5.55033e-2f);
    p = fmaf(p, f, 2.40226e-1f);
    p = fmaf(p, f, 6.93147e-1f);
    p = fmaf(p, f, 1.0f);
    return __int_as_float(((int)fi + 127) << 23) * p;
}

// ---------------- LayerNorm ----------------
__global__ __launch_bounds__(256)
void ln_kernel(const float* __restrict__ xq, const float* __restrict__ xk,
               const float* __restrict__ gamma, const float* __restrict__ beta)
{
    int row = blockIdx.x;
    const float* x; float* o;
    if (row < CM) { x = xq + (size_t)row*CD;       o = g_xq + (size_t)row*CD; }
    else          { x = xk + (size_t)(row-CM)*CD;  o = g_xk + (size_t)(row-CM)*CD; }
    int t = threadIdx.x;
    float2 v2 = ((const float2*)x)[t];
    float s  = v2.x + v2.y;
    float ss = v2.x*v2.x + v2.y*v2.y;
    #pragma unroll
    for (int off = 16; off; off >>= 1) {
        s  += __shfl_xor_sync(0xffffffffu, s,  off);
        ss += __shfl_xor_sync(0xffffffffu, ss, off);
    }
    __shared__ float sh_s[8], sh_ss[8];
    __shared__ float s_mean, s_rstd;
    int wid = t >> 5, lid = t & 31;
    if (lid == 0) { sh_s[wid] = s; sh_ss[wid] = ss; }
    __syncthreads();
    if (t < 32) {
        float a = (t < 8) ? sh_s[t]  : 0.f;
        float b = (t < 8) ? sh_ss[t] : 0.f;
        #pragma unroll
        for (int off = 4; off; off >>= 1) {
            a += __shfl_xor_sync(0xffffffffu, a, off);
            b += __shfl_xor_sync(0xffffffffu, b, off);
        }
        if (t == 0) {
            float mean = a * (1.0f/CD);
            float var  = b * (1.0f/CD) - mean*mean;
            s_mean = mean;
            s_rstd = rsqrtf(var + 1e-6f);
        }
    }
    __syncthreads();
    float mean = s_mean, rstd = s_rstd;
    float2 g2 = ((const float2*)gamma)[t];
    float2 b2 = ((const float2*)beta)[t];
    float2 o2;
    o2.x = (v2.x - mean) * rstd * g2.x + b2.x;
    o2.y = (v2.y - mean) * rstd * g2.y + b2.y;
    ((float2*)o)[t] = o2;
}

// ---------------- bf16x3 mma NT GEMM, double-buffered ----------------------
// modes: 0 q(scale 1/8)  1 k  2 v  3 gate(sigmoid)  4 out  5 scores(+stats, packed exp)
__global__ __launch_bounds__(256, 2)
void mma_gemm(int mode, const float* __restrict__ Wext,
              const float* __restrict__ bias, int act,
              float* __restrict__ Cext)
{
    __shared__ uint32_t Ah[2][128][RS], Al[2][128][RS];
    __shared__ uint32_t Bh[2][128][RS], Bl[2][128][RS];

    const float *A, *B; float *C = nullptr; int K, ldc = CD; float scale = 1.0f;
    int z = 0;
    if (mode == 5) {
        z = blockIdx.z;
        int b = z >> 3, h = z & 7;
        A = g_q + (size_t)b*CS*CD + h*CDK;
        B = g_k + (size_t)b*CS*CD + h*CDK;
        K = CDK;
    } else {
        switch (mode) {
            case 0: A = g_xq; C = g_q;    scale = 0.125f; break;
            case 1: A = g_xk; C = g_k;    break;
            case 2: A = g_xk; C = g_v;    break;
            case 3: A = g_xq; C = g_gate; break;
            default: A = g_ao; C = Cext;  break;
        }
        B = Wext; K = CD;
    }
    int tid = threadIdx.x, wid = tid >> 5, lane = tid & 31;
    int wm = wid & 1, wn = wid >> 1;          // warp tile 64m x 32n
    int m0 = blockIdx.y * 128, n0 = blockIdx.x * 128;
    const float* Ag = A + (size_t)m0 * CD;
    const float* Bg = B + (size_t)n0 * CD;

    int lr = tid >> 2;                 // 0..63
    int lc = (tid & 3) * 4;            // k offset 0,4,8,12
    int kp = (tid & 3) * 2;            // pair idx 0,2,4,6
    int qr = lane >> 2, qc = lane & 3;

    const uint32_t BUF = 128*RS*4;
    uint32_t aAh = s2u(Ah), aAl = s2u(Al), aBh = s2u(Bh), aBl = s2u(Bl);
    uint32_t offA = (uint32_t)(lane & 15) * (RS*4) + (uint32_t)((lane >> 4) & 1) * 16;
    uint32_t offB = (uint32_t)((lane & 7) + ((lane >> 4) & 1) * 8) * (RS*4)
                  + (uint32_t)((lane >> 3) & 1) * 16;

    float acc[4][4][4];
    #pragma unroll
    for (int i = 0; i < 4; i++)
        #pragma unroll
        for (int j = 0; j < 4; j++)
            #pragma unroll
            for (int e = 0; e < 4; e++) acc[i][j][e] = 0.f;

    float4 pa0 = *(const float4*)(Ag + (size_t)lr*CD + lc);
    float4 pa1 = *(const float4*)(Ag + (size_t)(lr+64)*CD + lc);
    float4 pb0 = *(const float4*)(Bg + (size_t)lr*CD + lc);
    float4 pb1 = *(const float4*)(Bg + (size_t)(lr+64)*CD + lc);
    const int NC = K / 16;

    {
        uint2 h, l;
        split2(pa0.x, pa0.y, h.x, l.x); split2(pa0.z, pa0.w, h.y, l.y);
        *(uint2*)&Ah[0][lr][kp] = h; *(uint2*)&Al[0][lr][kp] = l;
        split2(pa1.x, pa1.y, h.x, l.x); split2(pa1.z, pa1.w, h.y, l.y);
        *(uint2*)&Ah[0][lr+64][kp] = h; *(uint2*)&Al[0][lr+64][kp] = l;
        split2(pb0.x, pb0.y, h.x, l.x); split2(pb0.z, pb0.w, h.y, l.y);
        *(uint2*)&Bh[0][lr][kp] = h; *(uint2*)&Bl[0][lr][kp] = l;
        split2(pb1.x, pb1.y, h.x, l.x); split2(pb1.z, pb1.w, h.y, l.y);
        *(uint2*)&Bh[0][lr+64][kp] = h; *(uint2*)&Bl[0][lr+64][kp] = l;
    }
    if (NC > 1) {
        int k0 = 16 + lc;
        pa0 = *(const float4*)(Ag + (size_t)lr*CD + k0);
        pa1 = *(const float4*)(Ag + (size_t)(lr+64)*CD + k0);
        pb0 = *(const float4*)(Bg + (size_t)lr*CD + k0);
        pb1 = *(const float4*)(Bg + (size_t)(lr+64)*CD + k0);
    }
    __syncthreads();

    for (int c = 0; c < NC; c++) {
        uint32_t cb = (uint32_t)(c & 1) * BUF;
        uint32_t bh[4][2], bl[4][2];
        #pragma unroll
        for (int ntp = 0; ntp < 2; ntp++) {
            uint32_t nbase = (uint32_t)(wn*32 + ntp*16) * (RS*4);
            ldsm4(bh[2*ntp][0], bh[2*ntp][1], bh[2*ntp+1][0], bh[2*ntp+1][1], aBh + cb + nbase + offB);
            ldsm4(bl[2*ntp][0], bl[2*ntp][1], bl[2*ntp+1][0], bl[2*ntp+1][1], aBl + cb + nbase + offB);
        }
        #pragma unroll
        for (int mt = 0; mt < 4; mt++) {
            uint32_t rbase = (uint32_t)(wm*64 + mt*16) * (RS*4);
            uint32_t ah0, ah1, ah2, ah3, al0, al1, al2, al3;
            ldsm4(ah0, ah1, ah2, ah3, aAh + cb + rbase + offA);
            ldsm4(al0, al1, al2, al3, aAl + cb + rbase + offA);
            #pragma unroll
            for (int nt = 0; nt < 4; nt++) {
                mma16(acc[mt][nt][0], acc[mt][nt][1], acc[mt][nt][2], acc[mt][nt][3],
                      ah0, ah1, ah2, ah3, bh[nt][0], bh[nt][1]);
                mma16(acc[mt][nt][0], acc[mt][nt][1], acc[mt][nt][2], acc[mt][nt][3],
                      ah0, ah1, ah2, ah3, bl[nt][0], bl[nt][1]);
                mma16(acc[mt][nt][0], acc[mt][nt][1], acc[mt][nt][2], acc[mt][nt][3],
                      al0, al1, al2, al3, bh[nt][0], bh[nt][1]);
            }
        }
        if (c + 1 < NC) {
            int ni = (c & 1) ^ 1;
            uint2 h, l;
            split2(pa0.x, pa0.y, h.x, l.x); split2(pa0.z, pa0.w, h.y, l.y);
            *(uint2*)&Ah[ni][lr][kp] = h; *(uint2*)&Al[ni][lr][kp] = l;
            split2(pa1.x, pa1.y, h.x, l.x); split2(pa1.z, pa1.w, h.y, l.y);
            *(uint2*)&Ah[ni][lr+64][kp] = h; *(uint2*)&Al[ni][lr+64][kp] = l;
            split2(pb0.x, pb0.y, h.x, l.x); split2(pb0.z, pb0.w, h.y, l.y);
            *(uint2*)&Bh[ni][lr][kp] = h; *(uint2*)&Bl[ni][lr][kp] = l;
            split2(pb1.x, pb1.y, h.x, l.x); split2(pb1.z, pb1.w, h.y, l.y);
            *(uint2*)&Bh[ni][lr+64][kp] = h; *(uint2*)&Bl[ni][lr+64][kp] = l;
            if (c + 2 < NC) {
                int k0 = (c+2)*16 + lc;
                pa0 = *(const float4*)(Ag + (size_t)lr*CD + k0);
                pa1 = *(const float4*)(Ag + (size_t)(lr+64)*CD + k0);
                pb0 = *(const float4*)(Bg + (size_t)lr*CD + k0);
                pb1 = *(const float4*)(Bg + (size_t)(lr+64)*CD + k0);
            }
        }
        __syncthreads();
    }

    if (mode != 5) {
        // standard epilogue: store C (fp32)
        #pragma unroll
        for (int mt = 0; mt < 4; mt++) {
            int r = m0 + wm*64 + mt*16 + qr;
            #pragma unroll
            for (int nt = 0; nt < 4; nt++) {
                int col = n0 + wn*32 + nt*8 + qc*2;
                float o0 = acc[mt][nt][0]*scale, o1 = acc[mt][nt][1]*scale;
                float o2 = acc[mt][nt][2]*scale, o3 = acc[mt][nt][3]*scale;
                if (bias) {
                    float b0 = bias[col], b1 = bias[col+1];
                    o0 += b0; o1 += b1; o2 += b0; o3 += b1;
                }
                if (act == 1) {
                    o0 = 1.0f/(1.0f + __expf(-o0));
                    o1 = 1.0f/(1.0f + __expf(-o1));
                    o2 = 1.0f/(1.0f + __expf(-o2));
                    o3 = 1.0f/(1.0f + __expf(-o3));
                }
                *(float2*)(C + (size_t)r*ldc + col)     = make_float2(o0, o1);
                *(float2*)(C + (size_t)(r+8)*ldc + col) = make_float2(o2, o3);
            }
        }
    } else {
        // scores: ex = exp(x); stats partials; store split(ex^2) packed pairs
        float csl[4][2];
        #pragma unroll
        for (int nt = 0; nt < 4; nt++) { csl[nt][0] = 0.f; csl[nt][1] = 0.f; }
        #pragma unroll
        for (int mt = 0; mt < 4; mt++) {
            float ex[4][4];
            #pragma unroll
            for (int nt = 0; nt < 4; nt++)
                #pragma unroll
                for (int e = 0; e < 4; e++) ex[nt][e] = fast_exp(acc[mt][nt][e]);
            float r0 = 0.f, r1 = 0.f;
            #pragma unroll
            for (int nt = 0; nt < 4; nt++) {
                r0 += ex[nt][0] + ex[nt][1];
                r1 += ex[nt][2] + ex[nt][3];
                csl[nt][0] += ex[nt][0] + ex[nt][2];
                csl[nt][1] += ex[nt][1] + ex[nt][3];
            }
            r0 += __shfl_xor_sync(0xffffffffu, r0, 1);
            r0 += __shfl_xor_sync(0xffffffffu, r0, 2);
            r1 += __shfl_xor_sync(0xffffffffu, r1, 1);
            r1 += __shfl_xor_sync(0xffffffffu, r1, 2);
            int row0 = m0 + wm*64 + mt*16 + qr;
            if (qc == 0) {
                int rslot = blockIdx.x * 4 + wn;
                g_rpart[((size_t)(z*CS + row0) << 6) + rslot]     = r0;
                g_rpart[((size_t)(z*CS + row0 + 8) << 6) + rslot] = r1;
            }
            #pragma unroll
            for (int nt = 0; nt < 4; nt++) {
                int colp = (n0 >> 1) + wn*16 + nt*4 + qc;
                uint2 pk;
                split2(ex[nt][0]*ex[nt][0], ex[nt][1]*ex[nt][1], pk.x, pk.y);
                g_p[(size_t)(z*CS + row0)*CSP + colp] = pk;
                split2(ex[nt][2]*ex[nt][2], ex[nt][3]*ex[nt][3], pk.x, pk.y);
                g_p[(size_t)(z*CS + row0 + 8)*CSP + colp] = pk;
            }
        }
        #pragma unroll
        for (int nt = 0; nt < 4; nt++) {
            #pragma unroll
            for (int j = 0; j < 2; j++) {
                float v = csl[nt][j];
                v += __shfl_xor_sync(0xffffffffu, v, 4);
                v += __shfl_xor_sync(0xffffffffu, v, 8);
                v += __shfl_xor_sync(0xffffffffu, v, 16);
                if (qr == 0) {
                    int cslot = blockIdx.y * 2 + wm;
                    int col = n0 + wn*32 + nt*8 + qc*2 + j;
                    g_cpart[((size_t)(z*CS + col) << 5) + cslot] = v;
                }
            }
        }
    }
}

// ---------------- finalize: reduce partials -> reciprocals ------------------
__global__ __launch_bounds__(256)
void finalize_kernel()
{
    int i = blockIdx.x * 256 + threadIdx.x;
    if (i < CBH*CS) {
        const float4* p = (const float4*)(g_rpart + ((size_t)i << 6));
        float s = 0.f;
        #pragma unroll
        for (int j = 0; j < 16; j++) {
            float4 v = p[j];
            s += v.x + v.y + v.z + v.w;
        }
        g_rsum[i] = 1.0f / s;
    } else {
        i -= CBH*CS;
        const float4* p = (const float4*)(g_cpart + ((size_t)i << 5));
        float s = 0.f;
        #pragma unroll
        for (int j = 0; j < 8; j++) {
            float4 v = p[j];
            s += v.x + v.y + v.z + v.w;
        }
        g_csum[i] = 1.0f / s;
    }
}

// ---------------- V transpose with ci folded, packed split output -----------
__global__ __launch_bounds__(256)
void vtrans_ci()
{
    __shared__ float tile[64][65];
    int z = blockIdx.y, b = z >> 3, h = z & 7;
    int t0 = blockIdx.x * 64;
    const float* src = g_v + (size_t)b*CS*CD + h*CDK;
    int tid = threadIdx.x;
    #pragma unroll
    for (int i = 0; i < 16; i++) {
        int idx = tid + i*256;
        int tr = idx >> 6, d = idx & 63;
        tile[tr][d] = src[(size_t)(t0 + tr)*CD + d] * g_csum[z*CS + t0 + tr];
    }
    __syncthreads();
    #pragma unroll
    for (int i = 0; i < 8; i++) {
        int idx = tid + i*256;
        int d = idx >> 5, tp = idx & 31;
        uint2 pk;
        split2(tile[2*tp][d], tile[2*tp+1][d], pk.x, pk.y);
        g_vtp[((size_t)z*CDK + d)*CSP + (t0 >> 1) + tp] = pk;
    }
}

// ---------------- PV: pure pre-split GEMM, epilogue ri*gate -----------------
__global__ __launch_bounds__(256)
void pv_kernel()
{
    __shared__ uint32_t Ph[2][128][RS], Pl[2][128][RS];
    __shared__ uint32_t Vh[2][64][RS],  Vl[2][64][RS];
    int z = blockIdx.y, b = z >> 3, h = z & 7;
    int s0 = blockIdx.x * 128;
    int tid = threadIdx.x, wid = tid >> 5, lane = tid & 31;
    int wm = wid & 3, wn = wid >> 2;
    int qr = lane >> 2, qc = lane & 3;

    int pr = tid >> 1;                 // P row 0..127
    int pp = (tid & 1) * 4;            // pair base 0/4
    int vr = tid >> 2;                 // V^T row (dk) 0..63
    int vp = (tid & 3) * 2;            // pair base 0,2,4,6
    const uint2* aph = g_p   + (size_t)(z*CS + s0 + pr)*CSP;
    const uint2* avh = g_vtp + ((size_t)z*CDK + vr)*CSP;

    const uint32_t BUFP = 128*RS*4, BUFV = 64*RS*4;
    uint32_t aPh = s2u(Ph), aPl = s2u(Pl), aVh = s2u(Vh), aVl = s2u(Vl);
    uint32_t offA = (uint32_t)(lane & 15) * (RS*4) + (uint32_t)((lane >> 4) & 1) * 16;
    uint32_t offB = (uint32_t)((lane & 7) + ((lane >> 4) & 1) * 8) * (RS*4)
                  + (uint32_t)((lane >> 3) & 1) * 16;

    float acc[2][4][4];
    #pragma unroll
    for (int i = 0; i < 2; i++)
        #pragma unroll
        for (int j = 0; j < 4; j++)
            #pragma unroll
            for (int e = 0; e < 4; e++) acc[i][j][e] = 0.f;

    uint4 rp0, rp1, rv0;
    #define PLOAD(c) do { \
        rp0 = *(const uint4*)(aph + (c)*8 + pp); \
        rp1 = *(const uint4*)(aph + (c)*8 + pp + 2); \
        rv0 = *(const uint4*)(avh + (c)*8 + vp); \
    } while (0)
    #define PSTAGE(bi) do { \
        uint4 th = make_uint4(rp0.x, rp0.z, rp1.x, rp1.z); \
        uint4 tl = make_uint4(rp0.y, rp0.w, rp1.y, rp1.w); \
        *(uint4*)&Ph[bi][pr][pp] = th; \
        *(uint4*)&Pl[bi][pr][pp] = tl; \
        *(uint2*)&Vh[bi][vr][vp] = make_uint2(rv0.x, rv0.z); \
        *(uint2*)&Vl[bi][vr][vp] = make_uint2(rv0.y, rv0.w); \
    } while (0)

    const int NC = CS / 16;            // 128 chunks
    PLOAD(0); PSTAGE(0); PLOAD(1);
    __syncthreads();

    for (int c = 0; c < NC; c++) {
        uint32_t cbP = (uint32_t)(c & 1) * BUFP;
        uint32_t cbV = (uint32_t)(c & 1) * BUFV;
        uint32_t bh[4][2], bl[4][2];
        #pragma unroll
        for (int ntp = 0; ntp < 2; ntp++) {
            uint32_t nbase = (uint32_t)(wn*32 + ntp*16) * (RS*4);
            ldsm4(bh[2*ntp][0], bh[2*ntp][1], bh[2*ntp+1][0], bh[2*ntp+1][1], aVh + cbV + nbase + offB);
            ldsm4(bl[2*ntp][0], bl[2*ntp][1], bl[2*ntp+1][0], bl[2*ntp+1][1], aVl + cbV + nbase + offB);
        }
        #pragma unroll
        for (int mt = 0; mt < 2; mt++) {
            uint32_t rbase = (uint32_t)(wm*32 + mt*16) * (RS*4);
            uint32_t ah0, ah1, ah2, ah3, al0, al1, al2, al3;
            ldsm4(ah0, ah1, ah2, ah3, aPh + cbP + rbase + offA);
            ldsm4(al0, al1, al2, al3, aPl + cbP + rbase + offA);
            #pragma unroll
            for (int nt = 0; nt < 4; nt++) {
                mma16(acc[mt][nt][0], acc[mt][nt][1], acc[mt][nt][2], acc[mt][nt][3],
                      ah0, ah1, ah2, ah3, bh[nt][0], bh[nt][1]);
                mma16(acc[mt][nt][0], acc[mt][nt][1], acc[mt][nt][2], acc[mt][nt][3],
                      ah0, ah1, ah2, ah3, bl[nt][0], bl[nt][1]);
                mma16(acc[mt][nt][0], acc[mt][nt][1], acc[mt][nt][2], acc[mt][nt][3],
                      al0, al1, al2, al3, bh[nt][0], bh[nt][1]);
            }
        }
        if (c + 1 < NC) {
            PSTAGE((c+1) & 1);
            if (c + 2 < NC) PLOAD(c+2);
        }
        __syncthreads();
    }
    // epilogue: * rsum_inv, * gate -> g_ao
    #pragma unroll
    for (int mt = 0; mt < 2; mt++) {
        #pragma unroll
        for (int half = 0; half < 2; half++) {
            int srow = s0 + wm*32 + mt*16 + qr + half*8;
            float ri = g_rsum[(size_t)z*CS + srow];
            const float* grow = g_gate + ((size_t)b*CS + srow)*CD + h*CDK;
            float* orow       = g_ao   + ((size_t)b*CS + srow)*CD + h*CDK;
            #pragma unroll
            for (int nt = 0; nt < 4; nt++) {
                int col = wn*32 + nt*8 + qc*2;
                float o0 = acc[mt][nt][half*2+0] * ri;
                float o1 = acc[mt][nt][half*2+1] * ri;
                float2 gg = *(const float2*)(grow + col);
                *(float2*)(orow + col) = make_float2(o0*gg.x, o1*gg.y);
            }
        }
    }
}

// ---------------- launch ----------------
extern "C" void kernel_launch(void* const* d_in, const int* in_sizes, int n_in,
                              void* d_out, int out_size)
{
    const float* x_q   = (const float*)d_in[0];
    const float* x_k   = (const float*)d_in[1];
    const float* Wq    = (const float*)d_in[2];
    const float* Wk    = (const float*)d_in[3];
    const float* Wv    = (const float*)d_in[4];
    const float* Wg    = (const float*)d_in[5];
    const float* bg    = (const float*)d_in[6];
    const float* Wo    = (const float*)d_in[7];
    const float* bo    = (const float*)d_in[8];
    const float* gamma = (const float*)d_in[9];
    const float* beta  = (const float*)d_in[10];
    float* out = (float*)d_out;

    // 1. LayerNorm
    ln_kernel<<<2*CM, 256>>>(x_q, x_k, gamma, beta);

    // 2. Projections; q pre-scaled by 1/8
    dim3 gg(CD/128, CM/128);                          // (4, 64)
    mma_gemm<<<gg, 256>>>(0, Wq, nullptr, 0, nullptr);
    mma_gemm<<<gg, 256>>>(1, Wk, nullptr, 0, nullptr);
    mma_gemm<<<gg, 256>>>(2, Wv, nullptr, 0, nullptr);
    mma_gemm<<<gg, 256>>>(3, Wg, bg, 1, nullptr);

    // 3. Scores + stats, store packed split(exp(2x))
    mma_gemm<<<dim3(CS/128, CS/128, CBH), 256>>>(5, nullptr, nullptr, 0, nullptr);

    // 4. Reduce partials -> reciprocal sums
    finalize_kernel<<<(2*CBH*CS)/256, 256>>>();

    // 5. V transpose with ci folded, packed split
    vtrans_ci<<<dim3(CS/64, CBH), 256>>>();

    // 6. PV: pure pre-split GEMM, ri*gate fused
    pv_kernel<<<dim3(CS/128, CBH), 256>>>();

    // 7. Output projection + bias -> d_out
    mma_gemm<<<gg, 256>>>(4, Wo, bo, 0, out);
}

// round 11
// speedup vs baseline: 1.7928x; 1.1152x over previous
#include <cuda_runtime.h>
#include <cuda_bf16.h>
#include <cstdint>
#include <math.h>

#define CB 4
#define CS 2048
#define CD 512
#define CH 8
#define CDK 64
#define CM (CB*CS)      // 8192
#define CBH (CB*CH)     // 32
#define CDP (CD/2)      // 256 pairs per D row
#define CSP (CS/2)      // 1024 pairs per score row

// ---------------- scratch (device globals: allocation-free) ----------------
static __device__ uint2 g_xqp[CM*CDP];                // LN(xq) packed split
static __device__ uint2 g_xkp[CM*CDP];                // LN(xk) packed split
static __device__ uint2 g_wp[5][CD*CDP];              // Wq,Wk,Wv,Wg,Wo packed split
static __device__ uint2 g_qp[CM*CDP];                 // q/8 packed split
static __device__ uint2 g_kp[CM*CDP];                 // k packed split
static __device__ float g_v[CM*CD];
static __device__ float g_gate[CM*CD];
static __device__ uint2 g_aop[CM*CDP];                // attn-out*ri*gate packed split
static __device__ uint2 g_p[(size_t)CBH*CS*CSP];      // split(exp(2x)) packed
static __device__ uint2 g_vtp[CBH*CDK*CSP];           // split(V^T * ci) packed
static __device__ float g_rpart[(size_t)CBH*CS*64];
static __device__ float g_cpart[(size_t)CBH*CS*32];
static __device__ float g_rsum[CBH*CS];
static __device__ float g_csum[CBH*CS];

// ---------------- helpers ----------------
__device__ __forceinline__ uint32_t s2u(const void* p) {
    return (uint32_t)__cvta_generic_to_shared(p);
}
__device__ __forceinline__ void split2(float x0, float x1, uint32_t &hi, uint32_t &lo) {
    __nv_bfloat16 h0 = __float2bfloat16_rn(x0);
    __nv_bfloat16 h1 = __float2bfloat16_rn(x1);
    float r0 = x0 - __bfloat162float(h0);
    float r1 = x1 - __bfloat162float(h1);
    __nv_bfloat16 l0 = __float2bfloat16_rn(r0);
    __nv_bfloat16 l1 = __float2bfloat16_rn(r1);
    hi = (uint32_t)__bfloat16_as_ushort(h0) | ((uint32_t)__bfloat16_as_ushort(h1) << 16);
    lo = (uint32_t)__bfloat16_as_ushort(l0) | ((uint32_t)__bfloat16_as_ushort(l1) << 16);
}
__device__ __forceinline__ void mma16(float &c0, float &c1, float &c2, float &c3,
                                      uint32_t a0, uint32_t a1, uint32_t a2, uint32_t a3,
                                      uint32_t b0, uint32_t b1) {
    asm("mma.sync.aligned.m16n8k16.row.col.f32.bf16.bf16.f32 "
        "{%0,%1,%2,%3}, {%4,%5,%6,%7}, {%8,%9}, {%0,%1,%2,%3};"
        : "+f"(c0), "+f"(c1), "+f"(c2), "+f"(c3)
        : "r"(a0), "r"(a1), "r"(a2), "r"(a3), "r"(b0), "r"(b1));
}
__device__ __forceinline__ void ldsm4(uint32_t &r0, uint32_t &r1, uint32_t &r2, uint32_t &r3,
                                      uint32_t addr) {
    asm volatile("ldmatrix.sync.aligned.m8n8.x4.shared.b16 {%0,%1,%2,%3}, [%4];"
                 : "=r"(r0), "=r"(r1), "=r"(r2), "=r"(r3) : "r"(addr));
}
#define RS 12   // SMEM row stride in uint32 (48B, conflict-free)

__device__ __forceinline__ float fast_exp(float x) {
    x = fmaxf(x, -80.0f);
    float t  = x * 1.4426950408889634f;
    float fi = floorf(t);
    float f  = t - fi;
    float p  = 1.53533e-4f;
    p = fmaf(p, f, 1.33989e-3f);
    p = fmaf(p, f, 9.61844e-3f);
    p = fmaf(p, f, 5.55033e-2f);
    p = fmaf(p, f, 2.40226e-1f);
    p = fmaf(p, f, 6.93147e-1f);
    p = fmaf(p, f, 1.0f);
    return __int_as_float(((int)fi + 127) << 23) * p;
}

// ---------------- LayerNorm -> packed split ----------------
__global__ __launch_bounds__(256)
void ln_kernel(const float* __restrict__ xq, const float* __restrict__ xk,
               const float* __restrict__ gamma, const float* __restrict__ beta)
{
    int row = blockIdx.x;
    const float* x; uint2* o;
    if (row < CM) { x = xq + (size_t)row*CD;       o = g_xqp + (size_t)row*CDP; }
    else          { x = xk + (size_t)(row-CM)*CD;  o = g_xkp + (size_t)(row-CM)*CDP; }
    int t = threadIdx.x;
    float2 v2 = ((const float2*)x)[t];
    float s  = v2.x + v2.y;
    float ss = v2.x*v2.x + v2.y*v2.y;
    #pragma unroll
    for (int off = 16; off; off >>= 1) {
        s  += __shfl_xor_sync(0xffffffffu, s,  off);
        ss += __shfl_xor_sync(0xffffffffu, ss, off);
    }
    __shared__ float sh_s[8], sh_ss[8];
    __shared__ float s_mean, s_rstd;
    int wid = t >> 5, lid = t & 31;
    if (lid == 0) { sh_s[wid] = s; sh_ss[wid] = ss; }
    __syncthreads();
    if (t < 32) {
        float a = (t < 8) ? sh_s[t]  : 0.f;
        float b = (t < 8) ? sh_ss[t] : 0.f;
        #pragma unroll
        for (int off = 4; off; off >>= 1) {
            a += __shfl_xor_sync(0xffffffffu, a, off);
            b += __shfl_xor_sync(0xffffffffu, b, off);
        }
        if (t == 0) {
            float mean = a * (1.0f/CD);
            float var  = b * (1.0f/CD) - mean*mean;
            s_mean = mean;
            s_rstd = rsqrtf(var + 1e-6f);
        }
    }
    __syncthreads();
    float mean = s_mean, rstd = s_rstd;
    float2 g2 = ((const float2*)gamma)[t];
    float2 b2 = ((const float2*)beta)[t];
    float o0 = (v2.x - mean) * rstd * g2.x + b2.x;
    float o1 = (v2.y - mean) * rstd * g2.y + b2.y;
    uint2 pk;
    split2(o0, o1, pk.x, pk.y);
    o[t] = pk;
}

// ---------------- weight split: W[5] -> packed pairs ------------------------
__global__ __launch_bounds__(256)
void wsplit_kernel(const float* __restrict__ Wq, const float* __restrict__ Wk,
                   const float* __restrict__ Wv, const float* __restrict__ Wg,
                   const float* __restrict__ Wo)
{
    int m = blockIdx.y;
    const float* W = (m == 0) ? Wq : (m == 1) ? Wk : (m == 2) ? Wv : (m == 3) ? Wg : Wo;
    int idx = blockIdx.x * 256 + threadIdx.x;          // pair index, 0..CD*CDP-1
    float2 v = ((const float2*)W)[idx];
    uint2 pk;
    split2(v.x, v.y, pk.x, pk.y);
    g_wp[m][idx] = pk;
}

// ---------------- merged projections (packed operands) ----------------------
// z: 0 q(scale 1/8, packed out)  1 k(packed out)  2 v(fp32)  3 gate(sigmoid fp32)
__global__ __launch_bounds__(256, 2)
void proj_all(const float* __restrict__ bg)
{
    __shared__ uint32_t Ah[2][128][RS], Al[2][128][RS];
    __shared__ uint32_t Bh[2][128][RS], Bl[2][128][RS];
    int mode = blockIdx.z;
    const uint2* A = (mode == 0 || mode == 3) ? g_xqp : g_xkp;
    const uint2* B = g_wp[mode];
    float scale = (mode == 0) ? 0.125f : 1.0f;

    int tid = threadIdx.x, wid = tid >> 5, lane = tid & 31;
    int wm = wid & 1, wn = wid >> 1;
    int m0 = blockIdx.y * 128, n0 = blockIdx.x * 128;
    const uint2* Ag = A + (size_t)m0 * CDP;
    const uint2* Bg = B + (size_t)n0 * CDP;
    int lr = tid >> 2, kp = (tid & 3) * 2;
    int qr = lane >> 2, qc = lane & 3;

    const uint32_t BUF = 128*RS*4;
    uint32_t aAh = s2u(Ah), aAl = s2u(Al), aBh = s2u(Bh), aBl = s2u(Bl);
    uint32_t offA = (uint32_t)(lane & 15) * (RS*4) + (uint32_t)((lane >> 4) & 1) * 16;
    uint32_t offB = (uint32_t)((lane & 7) + ((lane >> 4) & 1) * 8) * (RS*4)
                  + (uint32_t)((lane >> 3) & 1) * 16;

    float acc[4][4][4];
    #pragma unroll
    for (int i = 0; i < 4; i++)
        #pragma unroll
        for (int j = 0; j < 4; j++)
            #pragma unroll
            for (int e = 0; e < 4; e++) acc[i][j][e] = 0.f;

    uint4 rA0, rA1, rB0, rB1;
    #define GLOAD(c) do { \
        size_t o0_ = (size_t)lr*CDP + (size_t)(c)*8 + kp; \
        size_t o1_ = (size_t)(lr+64)*CDP + (size_t)(c)*8 + kp; \
        rA0 = *(const uint4*)(Ag + o0_); rA1 = *(const uint4*)(Ag + o1_); \
        rB0 = *(const uint4*)(Bg + o0_); rB1 = *(const uint4*)(Bg + o1_); \
    } while (0)
    #define GSTAGE(bi) do { \
        *(uint2*)&Ah[bi][lr][kp]    = make_uint2(rA0.x, rA0.z); \
        *(uint2*)&Al[bi][lr][kp]    = make_uint2(rA0.y, rA0.w); \
        *(uint2*)&Ah[bi][lr+64][kp] = make_uint2(rA1.x, rA1.z); \
        *(uint2*)&Al[bi][lr+64][kp] = make_uint2(rA1.y, rA1.w); \
        *(uint2*)&Bh[bi][lr][kp]    = make_uint2(rB0.x, rB0.z); \
        *(uint2*)&Bl[bi][lr][kp]    = make_uint2(rB0.y, rB0.w); \
        *(uint2*)&Bh[bi][lr+64][kp] = make_uint2(rB1.x, rB1.z); \
        *(uint2*)&Bl[bi][lr+64][kp] = make_uint2(rB1.y, rB1.w); \
    } while (0)

    const int NC = CD / 16;    // 32
    GLOAD(0); GSTAGE(0); GLOAD(1);
    __syncthreads();

    for (int c = 0; c < NC; c++) {
        uint32_t cb = (uint32_t)(c & 1) * BUF;
        uint32_t bh[4][2], bl[4][2];
        #pragma unroll
        for (int ntp = 0; ntp < 2; ntp++) {
            uint32_t nbase = (uint32_t)(wn*32 + ntp*16) * (RS*4);
            ldsm4(bh[2*ntp][0], bh[2*ntp][1], bh[2*ntp+1][0], bh[2*ntp+1][1], aBh + cb + nbase + offB);
            ldsm4(bl[2*ntp][0], bl[2*ntp][1], bl[2*ntp+1][0], bl[2*ntp+1][1], aBl + cb + nbase + offB);
        }
        #pragma unroll
        for (int mt = 0; mt < 4; mt++) {
            uint32_t rbase = (uint32_t)(wm*64 + mt*16) * (RS*4);
            uint32_t ah0, ah1, ah2, ah3, al0, al1, al2, al3;
            ldsm4(ah0, ah1, ah2, ah3, aAh + cb + rbase + offA);
            ldsm4(al0, al1, al2, al3, aAl + cb + rbase + offA);
            #pragma unroll
            for (int nt = 0; nt < 4; nt++) {
                mma16(acc[mt][nt][0], acc[mt][nt][1], acc[mt][nt][2], acc[mt][nt][3],
                      ah0, ah1, ah2, ah3, bh[nt][0], bh[nt][1]);
                mma16(acc[mt][nt][0], acc[mt][nt][1], acc[mt][nt][2], acc[mt][nt][3],
                      ah0, ah1, ah2, ah3, bl[nt][0], bl[nt][1]);
                mma16(acc[mt][nt][0], acc[mt][nt][1], acc[mt][nt][2], acc[mt][nt][3],
                      al0, al1, al2, al3, bh[nt][0], bh[nt][1]);
            }
        }
        if (c + 1 < NC) {
            GSTAGE((c+1) & 1);
            if (c + 2 < NC) GLOAD(c+2);
        }
        __syncthreads();
    }
    #undef GLOAD
    #undef GSTAGE

    // epilogue
    if (mode <= 1) {
        uint2* O = (mode == 0) ? g_qp : g_kp;
        #pragma unroll
        for (int mt = 0; mt < 4; mt++) {
            int r = m0 + wm*64 + mt*16 + qr;
            #pragma unroll
            for (int nt = 0; nt < 4; nt++) {
                int colp = (n0 >> 1) + wn*16 + nt*4 + qc;
                uint2 pk;
                split2(acc[mt][nt][0]*scale, acc[mt][nt][1]*scale, pk.x, pk.y);
                O[(size_t)r*CDP + colp] = pk;
                split2(acc[mt][nt][2]*scale, acc[mt][nt][3]*scale, pk.x, pk.y);
                O[(size_t)(r+8)*CDP + colp] = pk;
            }
        }
    } else {
        float* O = (mode == 2) ? g_v : g_gate;
        #pragma unroll
        for (int mt = 0; mt < 4; mt++) {
            int r = m0 + wm*64 + mt*16 + qr;
            #pragma unroll
            for (int nt = 0; nt < 4; nt++) {
                int col = n0 + wn*32 + nt*8 + qc*2;
                float o0 = acc[mt][nt][0], o1 = acc[mt][nt][1];
                float o2 = acc[mt][nt][2], o3 = acc[mt][nt][3];
                if (mode == 3) {
                    float b0 = bg[col], b1 = bg[col+1];
                    o0 = 1.0f/(1.0f + __expf(-(o0+b0)));
                    o1 = 1.0f/(1.0f + __expf(-(o1+b1)));
                    o2 = 1.0f/(1.0f + __expf(-(o2+b0)));
                    o3 = 1.0f/(1.0f + __expf(-(o3+b1)));
                }
                *(float2*)(O + (size_t)r*CD + col)     = make_float2(o0, o1);
                *(float2*)(O + (size_t)(r+8)*CD + col) = make_float2(o2, o3);
            }
        }
    }
}

// ---------------- scores + stats (packed q/k in, packed exp out) ------------
__global__ __launch_bounds__(256, 2)
void scores_stats()
{
    __shared__ uint32_t Ah[2][128][RS], Al[2][128][RS];
    __shared__ uint32_t Bh[2][128][RS], Bl[2][128][RS];
    int z = blockIdx.z, b = z >> 3, h = z & 7;
    int m0 = blockIdx.y * 128, n0 = blockIdx.x * 128;
    int tid = threadIdx.x, wid = tid >> 5, lane = tid & 31;
    int wm = wid & 1, wn = wid >> 1;
    int lr = tid >> 2, kp = (tid & 3) * 2;
    int qr = lane >> 2, qc = lane & 3;

    const uint2* Ag = g_qp + (size_t)(b*CS + m0)*CDP + h*32;
    const uint2* Bg = g_kp + (size_t)(b*CS + n0)*CDP + h*32;

    const uint32_t BUF = 128*RS*4;
    uint32_t aAh = s2u(Ah), aAl = s2u(Al), aBh = s2u(Bh), aBl = s2u(Bl);
    uint32_t offA = (uint32_t)(lane & 15) * (RS*4) + (uint32_t)((lane >> 4) & 1) * 16;
    uint32_t offB = (uint32_t)((lane & 7) + ((lane >> 4) & 1) * 8) * (RS*4)
                  + (uint32_t)((lane >> 3) & 1) * 16;

    float acc[4][4][4];
    #pragma unroll
    for (int i = 0; i < 4; i++)
        #pragma unroll
        for (int j = 0; j < 4; j++)
            #pragma unroll
            for (int e = 0; e < 4; e++) acc[i][j][e] = 0.f;

    uint4 rA0, rA1, rB0, rB1;
    #define SLOAD(c) do { \
        size_t o0_ = (size_t)lr*CDP + (size_t)(c)*8 + kp; \
        size_t o1_ = (size_t)(lr+64)*CDP + (size_t)(c)*8 + kp; \
        rA0 = *(const uint4*)(Ag + o0_); rA1 = *(const uint4*)(Ag + o1_); \
        rB0 = *(const uint4*)(Bg + o0_); rB1 = *(const uint4*)(Bg + o1_); \
    } while (0)
    #define SSTAGE(bi) do { \
        *(uint2*)&Ah[bi][lr][kp]    = make_uint2(rA0.x, rA0.z); \
        *(uint2*)&Al[bi][lr][kp]    = make_uint2(rA0.y, rA0.w); \
        *(uint2*)&Ah[bi][lr+64][kp] = make_uint2(rA1.x, rA1.z); \
        *(uint2*)&Al[bi][lr+64][kp] = make_uint2(rA1.y, rA1.w); \
        *(uint2*)&Bh[bi][lr][kp]    = make_uint2(rB0.x, rB0.z); \
        *(uint2*)&Bl[bi][lr][kp]    = make_uint2(rB0.y, rB0.w); \
        *(uint2*)&Bh[bi][lr+64][kp] = make_uint2(rB1.x, rB1.z); \
        *(uint2*)&Bl[bi][lr+64][kp] = make_uint2(rB1.y, rB1.w); \
    } while (0)

    const int NC = CDK / 16;   // 4
    SLOAD(0); SSTAGE(0); SLOAD(1);
    __syncthreads();

    for (int c = 0; c < NC; c++) {
        uint32_t cb = (uint32_t)(c & 1) * BUF;
        uint32_t bh[4][2], bl[4][2];
        #pragma unroll
        for (int ntp = 0; ntp < 2; ntp++) {
            uint32_t nbase = (uint32_t)(wn*32 + ntp*16) * (RS*4);
            ldsm4(bh[2*ntp][0], bh[2*ntp][1], bh[2*ntp+1][0], bh[2*ntp+1][1], aBh + cb + nbase + offB);
            ldsm4(bl[2*ntp][0], bl[2*ntp][1], bl[2*ntp+1][0], bl[2*ntp+1][1], aBl + cb + nbase + offB);
        }
        #pragma unroll
        for (int mt = 0; mt < 4; mt++) {
            uint32_t rbase = (uint32_t)(wm*64 + mt*16) * (RS*4);
            uint32_t ah0, ah1, ah2, ah3, al0, al1, al2, al3;
            ldsm4(ah0, ah1, ah2, ah3, aAh + cb + rbase + offA);
            ldsm4(al0, al1, al2, al3, aAl + cb + rbase + offA);
            #pragma unroll
            for (int nt = 0; nt < 4; nt++) {
                mma16(acc[mt][nt][0], acc[mt][nt][1], acc[mt][nt][2], acc[mt][nt][3],
                      ah0, ah1, ah2, ah3, bh[nt][0], bh[nt][1]);
                mma16(acc[mt][nt][0], acc[mt][nt][1], acc[mt][nt][2], acc[mt][nt][3],
                      ah0, ah1, ah2, ah3, bl[nt][0], bl[nt][1]);
                mma16(acc[mt][nt][0], acc[mt][nt][1], acc[mt][nt][2], acc[mt][nt][3],
                      al0, al1, al2, al3, bh[nt][0], bh[nt][1]);
            }
        }
        if (c + 1 < NC) {
            SSTAGE((c+1) & 1);
            if (c + 2 < NC) SLOAD(c+2);
        }
        __syncthreads();
    }
    #undef SLOAD
    #undef SSTAGE

    // epilogue: ex = exp(x); stats partials; store split(ex^2) packed
    float csl[4][2];
    #pragma unroll
    for (int nt = 0; nt < 4; nt++) { csl[nt][0] = 0.f; csl[nt][1] = 0.f; }
    #pragma unroll
    for (int mt = 0; mt < 4; mt++) {
        float ex[4][4];
        #pragma unroll
        for (int nt = 0; nt < 4; nt++)
            #pragma unroll
            for (int e = 0; e < 4; e++) ex[nt][e] = fast_exp(acc[mt][nt][e]);
        float r0 = 0.f, r1 = 0.f;
        #pragma unroll
        for (int nt = 0; nt < 4; nt++) {
            r0 += ex[nt][0] + ex[nt][1];
            r1 += ex[nt][2] + ex[nt][3];
            csl[nt][0] += ex[nt][0] + ex[nt][2];
            csl[nt][1] += ex[nt][1] + ex[nt][3];
        }
        r0 += __shfl_xor_sync(0xffffffffu, r0, 1);
        r0 += __shfl_xor_sync(0xffffffffu, r0, 2);
        r1 += __shfl_xor_sync(0xffffffffu, r1, 1);
        r1 += __shfl_xor_sync(0xffffffffu, r1, 2);
        int row0 = m0 + wm*64 + mt*16 + qr;
        if (qc == 0) {
            int rslot = blockIdx.x * 4 + wn;
            g_rpart[((size_t)(z*CS + row0) << 6) + rslot]     = r0;
            g_rpart[((size_t)(z*CS + row0 + 8) << 6) + rslot] = r1;
        }
        #pragma unroll
        for (int nt = 0; nt < 4; nt++) {
            int colp = (n0 >> 1) + wn*16 + nt*4 + qc;
            uint2 pk;
            split2(ex[nt][0]*ex[nt][0], ex[nt][1]*ex[nt][1], pk.x, pk.y);
            g_p[(size_t)(z*CS + row0)*CSP + colp] = pk;
            split2(ex[nt][2]*ex[nt][2], ex[nt][3]*ex[nt][3], pk.x, pk.y);
            g_p[(size_t)(z*CS + row0 + 8)*CSP + colp] = pk;
        }
    }
    #pragma unroll
    for (int nt = 0; nt < 4; nt++) {
        #pragma unroll
        for (int j = 0; j < 2; j++) {
            float v = csl[nt][j];
            v += __shfl_xor_sync(0xffffffffu, v, 4);
            v += __shfl_xor_sync(0xffffffffu, v, 8);
            v += __shfl_xor_sync(0xffffffffu, v, 16);
            if (qr == 0) {
                int cslot = blockIdx.y * 2 + wm;
                int col = n0 + wn*32 + nt*8 + qc*2 + j;
                g_cpart[((size_t)(z*CS + col) << 5) + cslot] = v;
            }
        }
    }
}

// ---------------- finalize: reduce partials -> reciprocals ------------------
__global__ __launch_bounds__(256)
void finalize_kernel()
{
    int i = blockIdx.x * 256 + threadIdx.x;
    if (i < CBH*CS) {
        const float4* p = (const float4*)(g_rpart + ((size_t)i << 6));
        float s = 0.f;
        #pragma unroll
        for (int j = 0; j < 16; j++) {
            float4 v = p[j];
            s += v.x + v.y + v.z + v.w;
        }
        g_rsum[i] = 1.0f / s;
    } else {
        i -= CBH*CS;
        const float4* p = (const float4*)(g_cpart + ((size_t)i << 5));
        float s = 0.f;
        #pragma unroll
        for (int j = 0; j < 8; j++) {
            float4 v = p[j];
            s += v.x + v.y + v.z + v.w;
        }
        g_csum[i] = 1.0f / s;
    }
}

// ---------------- V transpose with ci folded, packed split output -----------
__global__ __launch_bounds__(256)
void vtrans_ci()
{
    __shared__ float tile[64][65];
    int z = blockIdx.y, b = z >> 3, h = z & 7;
    int t0 = blockIdx.x * 64;
    const float* src = g_v + (size_t)b*CS*CD + h*CDK;
    int tid = threadIdx.x;
    #pragma unroll
    for (int i = 0; i < 16; i++) {
        int idx = tid + i*256;
        int tr = idx >> 6, d = idx & 63;
        tile[tr][d] = src[(size_t)(t0 + tr)*CD + d] * g_csum[z*CS + t0 + tr];
    }
    __syncthreads();
    #pragma unroll
    for (int i = 0; i < 8; i++) {
        int idx = tid + i*256;
        int d = idx >> 5, tp = idx & 31;
        uint2 pk;
        split2(tile[2*tp][d], tile[2*tp+1][d], pk.x, pk.y);
        g_vtp[((size_t)z*CDK + d)*CSP + (t0 >> 1) + tp] = pk;
    }
}

// ---------------- PV: pure pre-split GEMM, packed out -----------------------
__global__ __launch_bounds__(256)
void pv_kernel()
{
    __shared__ uint32_t Ph[2][128][RS], Pl[2][128][RS];
    __shared__ uint32_t Vh[2][64][RS],  Vl[2][64][RS];
    int z = blockIdx.y, b = z >> 3, h = z & 7;
    int s0 = blockIdx.x * 128;
    int tid = threadIdx.x, wid = tid >> 5, lane = tid & 31;
    int wm = wid & 3, wn = wid >> 2;
    int qr = lane >> 2, qc = lane & 3;

    int pr = tid >> 1;                 // P row 0..127
    int pp = (tid & 1) * 4;            // pair base 0/4
    int vr = tid >> 2;                 // V^T row (dk) 0..63
    int vp = (tid & 3) * 2;            // pair base 0,2,4,6
    const uint2* aph = g_p   + (size_t)(z*CS + s0 + pr)*CSP;
    const uint2* avh = g_vtp + ((size_t)z*CDK + vr)*CSP;

    const uint32_t BUFP = 128*RS*4, BUFV = 64*RS*4;
    uint32_t aPh = s2u(Ph), aPl = s2u(Pl), aVh = s2u(Vh), aVl = s2u(Vl);
    uint32_t offA = (uint32_t)(lane & 15) * (RS*4) + (uint32_t)((lane >> 4) & 1) * 16;
    uint32_t offB = (uint32_t)((lane & 7) + ((lane >> 4) & 1) * 8) * (RS*4)
                  + (uint32_t)((lane >> 3) & 1) * 16;

    float acc[2][4][4];
    #pragma unroll
    for (int i = 0; i < 2; i++)
        #pragma unroll
        for (int j = 0; j < 4; j++)
            #pragma unroll
            for (int e = 0; e < 4; e++) acc[i][j][e] = 0.f;

    uint4 rp0, rp1, rv0;
    #define PLOAD(c) do { \
        rp0 = *(const uint4*)(aph + (size_t)(c)*8 + pp); \
        rp1 = *(const uint4*)(aph + (size_t)(c)*8 + pp + 2); \
        rv0 = *(const uint4*)(avh + (size_t)(c)*8 + vp); \
    } while (0)
    #define PSTAGE(bi) do { \
        *(uint4*)&Ph[bi][pr][pp] = make_uint4(rp0.x, rp0.z, rp1.x, rp1.z); \
        *(uint4*)&Pl[bi][pr][pp] = make_uint4(rp0.y, rp0.w, rp1.y, rp1.w); \
        *(uint2*)&Vh[bi][vr][vp] = make_uint2(rv0.x, rv0.z); \
        *(uint2*)&Vl[bi][vr][vp] = make_uint2(rv0.y, rv0.w); \
    } while (0)

    const int NC = CS / 16;            // 128 chunks
    PLOAD(0); PSTAGE(0); PLOAD(1);
    __syncthreads();

    for (int c = 0; c < NC; c++) {
        uint32_t cbP = (uint32_t)(c & 1) * BUFP;
        uint32_t cbV = (uint32_t)(c & 1) * BUFV;
        uint32_t bh[4][2], bl[4][2];
        #pragma unroll
        for (int ntp = 0; ntp < 2; ntp++) {
            uint32_t nbase = (uint32_t)(wn*32 + ntp*16) * (RS*4);
            ldsm4(bh[2*ntp][0], bh[2*ntp][1], bh[2*ntp+1][0], bh[2*ntp+1][1], aVh + cbV + nbase + offB);
            ldsm4(bl[2*ntp][0], bl[2*ntp][1], bl[2*ntp+1][0], bl[2*ntp+1][1], aVl + cbV + nbase + offB);
        }
        #pragma unroll
        for (int mt = 0; mt < 2; mt++) {
            uint32_t rbase = (uint32_t)(wm*32 + mt*16) * (RS*4);
            uint32_t ah0, ah1, ah2, ah3, al0, al1, al2, al3;
            ldsm4(ah0, ah1, ah2, ah3, aPh + cbP + rbase + offA);
            ldsm4(al0, al1, al2, al3, aPl + cbP + rbase + offA);
            #pragma unroll
            for (int nt = 0; nt < 4; nt++) {
                mma16(acc[mt][nt][0], acc[mt][nt][1], acc[mt][nt][2], acc[mt][nt][3],
                      ah0, ah1, ah2, ah3, bh[nt][0], bh[nt][1]);
                mma16(acc[mt][nt][0], acc[mt][nt][1], acc[mt][nt][2], acc[mt][nt][3],
                      ah0, ah1, ah2, ah3, bl[nt][0], bl[nt][1]);
                mma16(acc[mt][nt][0], acc[mt][nt][1], acc[mt][nt][2], acc[mt][nt][3],
                      al0, al1, al2, al3, bh[nt][0], bh[nt][1]);
            }
        }
        if (c + 1 < NC) {
            PSTAGE((c+1) & 1);
            if (c + 2 < NC) PLOAD(c+2);
        }
        __syncthreads();
    }
    #undef PLOAD
    #undef PSTAGE
    // epilogue: * rsum_inv, * gate -> g_aop (packed split)
    #pragma unroll
    for (int mt = 0; mt < 2; mt++) {
        #pragma unroll
        for (int half = 0; half < 2; half++) {
            int srow = s0 + wm*32 + mt*16 + qr + half*8;
            float ri = g_rsum[(size_t)z*CS + srow];
            const float* grow = g_gate + ((size_t)b*CS + srow)*CD + h*CDK;
            uint2* orow       = g_aop  + ((size_t)b*CS + srow)*CDP + h*32;
            #pragma unroll
            for (int nt = 0; nt < 4; nt++) {
                int col = wn*32 + nt*8 + qc*2;
                float2 gg = *(const float2*)(grow + col);
                float o0 = acc[mt][nt][half*2+0] * ri * gg.x;
                float o1 = acc[mt][nt][half*2+1] * ri * gg.y;
                uint2 pk;
                split2(o0, o1, pk.x, pk.y);
                orow[col >> 1] = pk;
            }
        }
    }
}

// ---------------- output projection: packed A/B, bias -> d_out --------------
__global__ __launch_bounds__(256, 2)
void out_gemm(const float* __restrict__ bo, float* __restrict__ C)
{
    __shared__ uint32_t Ah[2][128][RS], Al[2][128][RS];
    __shared__ uint32_t Bh[2][128][RS], Bl[2][128][RS];
    int tid = threadIdx.x, wid = tid >> 5, lane = tid & 31;
    int wm = wid & 1, wn = wid >> 1;
    int m0 = blockIdx.y * 128, n0 = blockIdx.x * 128;
    const uint2* Ag = g_aop + (size_t)m0 * CDP;
    const uint2* Bg = g_wp[4] + (size_t)n0 * CDP;
    int lr = tid >> 2, kp = (tid & 3) * 2;
    int qr = lane >> 2, qc = lane & 3;

    const uint32_t BUF = 128*RS*4;
    uint32_t aAh = s2u(Ah), aAl = s2u(Al), aBh = s2u(Bh), aBl = s2u(Bl);
    uint32_t offA = (uint32_t)(lane & 15) * (RS*4) + (uint32_t)((lane >> 4) & 1) * 16;
    uint32_t offB = (uint32_t)((lane & 7) + ((lane >> 4) & 1) * 8) * (RS*4)
                  + (uint32_t)((lane >> 3) & 1) * 16;

    float acc[4][4][4];
    #pragma unroll
    for (int i = 0; i < 4; i++)
        #pragma unroll
        for (int j = 0; j < 4; j++)
            #pragma unroll
            for (int e = 0; e < 4; e++) acc[i][j][e] = 0.f;

    uint4 rA0, rA1, rB0, rB1;
    #define OLOAD(c) do { \
        size_t o0_ = (size_t)lr*CDP + (size_t)(c)*8 + kp; \
        size_t o1_ = (size_t)(lr+64)*CDP + (size_t)(c)*8 + kp; \
        rA0 = *(const uint4*)(Ag + o0_); rA1 = *(const uint4*)(Ag + o1_); \
        rB0 = *(const uint4*)(Bg + o0_); rB1 = *(const uint4*)(Bg + o1_); \
    } while (0)
    #define OSTAGE(bi) do { \
        *(uint2*)&Ah[bi][lr][kp]    = make_uint2(rA0.x, rA0.z); \
        *(uint2*)&Al[bi][lr][kp]    = make_uint2(rA0.y, rA0.w); \
        *(uint2*)&Ah[bi][lr+64][kp] = make_uint2(rA1.x, rA1.z); \
        *(uint2*)&Al[bi][lr+64][kp] = make_uint2(rA1.y, rA1.w); \
        *(uint2*)&Bh[bi][lr][kp]    = make_uint2(rB0.x, rB0.z); \
        *(uint2*)&Bl[bi][lr][kp]    = make_uint2(rB0.y, rB0.w); \
        *(uint2*)&Bh[bi][lr+64][kp] = make_uint2(rB1.x, rB1.z); \
        *(uint2*)&Bl[bi][lr+64][kp] = make_uint2(rB1.y, rB1.w); \
    } while (0)

    const int NC = CD / 16;
    OLOAD(0); OSTAGE(0); OLOAD(1);
    __syncthreads();

    for (int c = 0; c < NC; c++) {
        uint32_t cb = (uint32_t)(c & 1) * BUF;
        uint32_t bh[4][2], bl[4][2];
        #pragma unroll
        for (int ntp = 0; ntp < 2; ntp++) {
            uint32_t nbase = (uint32_t)(wn*32 + ntp*16) * (RS*4);
            ldsm4(bh[2*ntp][0], bh[2*ntp][1], bh[2*ntp+1][0], bh[2*ntp+1][1], aBh + cb + nbase + offB);
            ldsm4(bl[2*ntp][0], bl[2*ntp][1], bl[2*ntp+1][0], bl[2*ntp+1][1], aBl + cb + nbase + offB);
        }
        #pragma unroll
        for (int mt = 0; mt < 4; mt++) {
            uint32_t rbase = (uint32_t)(wm*64 + mt*16) * (RS*4);
            uint32_t ah0, ah1, ah2, ah3, al0, al1, al2, al3;
            ldsm4(ah0, ah1, ah2, ah3, aAh + cb + rbase + offA);
            ldsm4(al0, al1, al2, al3, aAl + cb + rbase + offA);
            #pragma unroll
            for (int nt = 0; nt < 4; nt++) {
                mma16(acc[mt][nt][0], acc[mt][nt][1], acc[mt][nt][2], acc[mt][nt][3],
                      ah0, ah1, ah2, ah3, bh[nt][0], bh[nt][1]);
                mma16(acc[mt][nt][0], acc[mt][nt][1], acc[mt][nt][2], acc[mt][nt][3],
                      ah0, ah1, ah2, ah3, bl[nt][0], bl[nt][1]);
                mma16(acc[mt][nt][0], acc[mt][nt][1], acc[mt][nt][2], acc[mt][nt][3],
                      al0, al1, al2, al3, bh[nt][0], bh[nt][1]);
            }
        }
        if (c + 1 < NC) {
            OSTAGE((c+1) & 1);
            if (c + 2 < NC) OLOAD(c+2);
        }
        __syncthreads();
    }
    #undef OLOAD
    #undef OSTAGE
    #pragma unroll
    for (int mt = 0; mt < 4; mt++) {
        int r = m0 + wm*64 + mt*16 + qr;
        #pragma unroll
        for (int nt = 0; nt < 4; nt++) {
            int col = n0 + wn*32 + nt*8 + qc*2;
            float b0 = bo[col], b1 = bo[col+1];
            *(float2*)(C + (size_t)r*CD + col) =
                make_float2(acc[mt][nt][0] + b0, acc[mt][nt][1] + b1);
            *(float2*)(C + (size_t)(r+8)*CD + col) =
                make_float2(acc[mt][nt][2] + b0, acc[mt][nt][3] + b1);
        }
    }
}

// ---------------- launch ----------------
extern "C" void kernel_launch(void* const* d_in, const int* in_sizes, int n_in,
                              void* d_out, int out_size)
{
    const float* x_q   = (const float*)d_in[0];
    const float* x_k   = (const float*)d_in[1];
    const float* Wq    = (const float*)d_in[2];
    const float* Wk    = (const float*)d_in[3];
    const float* Wv    = (const float*)d_in[4];
    const float* Wg    = (const float*)d_in[5];
    const float* bg    = (const float*)d_in[6];
    const float* Wo    = (const float*)d_in[7];
    const float* bo    = (const float*)d_in[8];
    const float* gamma = (const float*)d_in[9];
    const float* beta  = (const float*)d_in[10];
    float* out = (float*)d_out;

    // 1. LayerNorm (packed-split output) + weight split
    ln_kernel<<<2*CM, 256>>>(x_q, x_k, gamma, beta);
    wsplit_kernel<<<dim3(CD*CDP/256, 5), 256>>>(Wq, Wk, Wv, Wg, Wo);

    // 2. All projections, one launch (copy-staged)
    proj_all<<<dim3(CD/128, CM/128, 4), 256>>>(bg);

    // 3. Scores + stats (copy-staged), packed exp out
    scores_stats<<<dim3(CS/128, CS/128, CBH), 256>>>();

    // 4. Reduce partials -> reciprocal sums
    finalize_kernel<<<(2*CBH*CS)/256, 256>>>();

    // 5. V transpose with ci folded, packed split
    vtrans_ci<<<dim3(CS/64, CBH), 256>>>();

    // 6. PV (copy-staged), packed split out
    pv_kernel<<<dim3(CS/128, CBH), 256>>>();

    // 7. Output projection (copy-staged) + bias -> d_out
    out_gemm<<<dim3(CD/128, CM/128), 256>>>(bo, out);
}

// round 12
// speedup vs baseline: 1.9252x; 1.0738x over previous
#include <cuda_runtime.h>
#include <cuda_bf16.h>
#include <cuda_fp16.h>
#include <cstdint>
#include <math.h>

#define CB 4
#define CS 2048
#define CD 512
#define CH 8
#define CDK 64
#define CM (CB*CS)      // 8192
#define CBH (CB*CH)     // 32
#define CDP (CD/2)      // 256 pairs per D row
#define CSP (CS/2)      // 1024 pairs per score row

// P stored as exp(2x) * 2^-8 (fp16); V stored as v * ci * 2^8 (fp16 split).
// Product scale: 2^-8 * 2^8 = 1, so epilogue needs no correction.
#define PSCALE (1.0f/256.0f)
#define VSCALE 256.0f

// ---------------- scratch (device globals: allocation-free) ----------------
static __device__ uint2 g_xqp[CM*CDP];                // LN(xq) packed bf16 split
static __device__ uint2 g_xkp[CM*CDP];                // LN(xk) packed bf16 split
static __device__ uint2 g_wp[5][CD*CDP];              // weights packed bf16 split
static __device__ uint2 g_qp[CM*CDP];                 // q/8 packed bf16 split
static __device__ uint2 g_kp[CM*CDP];                 // k packed bf16 split
static __device__ float g_v[CM*CD];
static __device__ float g_gate[CM*CD];
static __device__ uint2 g_aop[CM*CDP];                // attn-out*ri*gate packed bf16 split
static __device__ uint32_t g_p[(size_t)CBH*CS*CSP];   // fp16x2: exp(2x)*2^-8  (256 MB)
static __device__ uint2 g_vtp[CBH*CDK*CSP];           // fp16 split: V^T * ci * 2^8
static __device__ float g_rpart[(size_t)CBH*CS*64];
static __device__ float g_cpart[(size_t)CBH*CS*32];
static __device__ float g_rsum[CBH*CS];
static __device__ float g_csum[CBH*CS];

// ---------------- helpers ----------------
__device__ __forceinline__ uint32_t s2u(const void* p) {
    return (uint32_t)__cvta_generic_to_shared(p);
}
__device__ __forceinline__ void split2(float x0, float x1, uint32_t &hi, uint32_t &lo) {
    __nv_bfloat16 h0 = __float2bfloat16_rn(x0);
    __nv_bfloat16 h1 = __float2bfloat16_rn(x1);
    float r0 = x0 - __bfloat162float(h0);
    float r1 = x1 - __bfloat162float(h1);
    __nv_bfloat16 l0 = __float2bfloat16_rn(r0);
    __nv_bfloat16 l1 = __float2bfloat16_rn(r1);
    hi = (uint32_t)__bfloat16_as_ushort(h0) | ((uint32_t)__bfloat16_as_ushort(h1) << 16);
    lo = (uint32_t)__bfloat16_as_ushort(l0) | ((uint32_t)__bfloat16_as_ushort(l1) << 16);
}
__device__ __forceinline__ uint32_t pack_h2(float x0, float x1) {
    __half2 h = __floats2half2_rn(x0, x1);
    return *(uint32_t*)&h;
}
__device__ __forceinline__ void splith2(float x0, float x1, uint32_t &hi, uint32_t &lo) {
    __half h0 = __float2half_rn(x0);
    __half h1 = __float2half_rn(x1);
    float r0 = x0 - __half2float(h0);
    float r1 = x1 - __half2float(h1);
    __half l0 = __float2half_rn(r0);
    __half l1 = __float2half_rn(r1);
    hi = (uint32_t)__half_as_ushort(h0) | ((uint32_t)__half_as_ushort(h1) << 16);
    lo = (uint32_t)__half_as_ushort(l0) | ((uint32_t)__half_as_ushort(l1) << 16);
}
__device__ __forceinline__ void mma16(float &c0, float &c1, float &c2, float &c3,
                                      uint32_t a0, uint32_t a1, uint32_t a2, uint32_t a3,
                                      uint32_t b0, uint32_t b1) {
    asm("mma.sync.aligned.m16n8k16.row.col.f32.bf16.bf16.f32 "
        "{%0,%1,%2,%3}, {%4,%5,%6,%7}, {%8,%9}, {%0,%1,%2,%3};"
        : "+f"(c0), "+f"(c1), "+f"(c2), "+f"(c3)
        : "r"(a0), "r"(a1), "r"(a2), "r"(a3), "r"(b0), "r"(b1));
}
__device__ __forceinline__ void mma16h(float &c0, float &c1, float &c2, float &c3,
                                       uint32_t a0, uint32_t a1, uint32_t a2, uint32_t a3,
                                       uint32_t b0, uint32_t b1) {
    asm("mma.sync.aligned.m16n8k16.row.col.f32.f16.f16.f32 "
        "{%0,%1,%2,%3}, {%4,%5,%6,%7}, {%8,%9}, {%0,%1,%2,%3};"
        : "+f"(c0), "+f"(c1), "+f"(c2), "+f"(c3)
        : "r"(a0), "r"(a1), "r"(a2), "r"(a3), "r"(b0), "r"(b1));
}
__device__ __forceinline__ void ldsm4(uint32_t &r0, uint32_t &r1, uint32_t &r2, uint32_t &r3,
                                      uint32_t addr) {
    asm volatile("ldmatrix.sync.aligned.m8n8.x4.shared.b16 {%0,%1,%2,%3}, [%4];"
                 : "=r"(r0), "=r"(r1), "=r"(r2), "=r"(r3) : "r"(addr));
}
#define RS 12   // SMEM row stride in uint32 (48B, conflict-free)

__device__ __forceinline__ float fast_exp(float x) {
    x = fmaxf(x, -80.0f);
    float t  = x * 1.4426950408889634f;
    float fi = floorf(t);
    float f  = t - fi;
    float p  = 1.53533e-4f;
    p = fmaf(p, f, 1.33989e-3f);
    p = fmaf(p, f, 9.61844e-3f);
    p = fmaf(p, f, 5.55033e-2f);
    p = fmaf(p, f, 2.40226e-1f);
    p = fmaf(p, f, 6.93147e-1f);
    p = fmaf(p, f, 1.0f);
    return __int_as_float(((int)fi + 127) << 23) * p;
}

// ---------------- LayerNorm -> packed split ----------------
__global__ __launch_bounds__(256)
void ln_kernel(const float* __restrict__ xq, const float* __restrict__ xk,
               const float* __restrict__ gamma, const float* __restrict__ beta)
{
    int row = blockIdx.x;
    const float* x; uint2* o;
    if (row < CM) { x = xq + (size_t)row*CD;       o = g_xqp + (size_t)row*CDP; }
    else          { x = xk + (size_t)(row-CM)*CD;  o = g_xkp + (size_t)(row-CM)*CDP; }
    int t = threadIdx.x;
    float2 v2 = ((const float2*)x)[t];
    float s  = v2.x + v2.y;
    float ss = v2.x*v2.x + v2.y*v2.y;
    #pragma unroll
    for (int off = 16; off; off >>= 1) {
        s  += __shfl_xor_sync(0xffffffffu, s,  off);
        ss += __shfl_xor_sync(0xffffffffu, ss, off);
    }
    __shared__ float sh_s[8], sh_ss[8];
    __shared__ float s_mean, s_rstd;
    int wid = t >> 5, lid = t & 31;
    if (lid == 0) { sh_s[wid] = s; sh_ss[wid] = ss; }
    __syncthreads();
    if (t < 32) {
        float a = (t < 8) ? sh_s[t]  : 0.f;
        float b = (t < 8) ? sh_ss[t] : 0.f;
        #pragma unroll
        for (int off = 4; off; off >>= 1) {
            a += __shfl_xor_sync(0xffffffffu, a, off);
            b += __shfl_xor_sync(0xffffffffu, b, off);
        }
        if (t == 0) {
            float mean = a * (1.0f/CD);
            float var  = b * (1.0f/CD) - mean*mean;
            s_mean = mean;
            s_rstd = rsqrtf(var + 1e-6f);
        }
    }
    __syncthreads();
    float mean = s_mean, rstd = s_rstd;
    float2 g2 = ((const float2*)gamma)[t];
    float2 b2 = ((const float2*)beta)[t];
    float o0 = (v2.x - mean) * rstd * g2.x + b2.x;
    float o1 = (v2.y - mean) * rstd * g2.y + b2.y;
    uint2 pk;
    split2(o0, o1, pk.x, pk.y);
    o[t] = pk;
}

// ---------------- weight split ----------------
__global__ __launch_bounds__(256)
void wsplit_kernel(const float* __restrict__ Wq, const float* __restrict__ Wk,
                   const float* __restrict__ Wv, const float* __restrict__ Wg,
                   const float* __restrict__ Wo)
{
    int m = blockIdx.y;
    const float* W = (m == 0) ? Wq : (m == 1) ? Wk : (m == 2) ? Wv : (m == 3) ? Wg : Wo;
    int idx = blockIdx.x * 256 + threadIdx.x;
    float2 v = ((const float2*)W)[idx];
    uint2 pk;
    split2(v.x, v.y, pk.x, pk.y);
    g_wp[m][idx] = pk;
}

// ---------------- merged projections (packed operands) ----------------------
__global__ __launch_bounds__(256, 2)
void proj_all(const float* __restrict__ bg)
{
    __shared__ uint32_t Ah[2][128][RS], Al[2][128][RS];
    __shared__ uint32_t Bh[2][128][RS], Bl[2][128][RS];
    int mode = blockIdx.z;
    const uint2* A = (mode == 0 || mode == 3) ? g_xqp : g_xkp;
    const uint2* B = g_wp[mode];
    float scale = (mode == 0) ? 0.125f : 1.0f;

    int tid = threadIdx.x, wid = tid >> 5, lane = tid & 31;
    int wm = wid & 1, wn = wid >> 1;
    int m0 = blockIdx.y * 128, n0 = blockIdx.x * 128;
    const uint2* Ag = A + (size_t)m0 * CDP;
    const uint2* Bg = B + (size_t)n0 * CDP;
    int lr = tid >> 2, kp = (tid & 3) * 2;
    int qr = lane >> 2, qc = lane & 3;

    const uint32_t BUF = 128*RS*4;
    uint32_t aAh = s2u(Ah), aAl = s2u(Al), aBh = s2u(Bh), aBl = s2u(Bl);
    uint32_t offA = (uint32_t)(lane & 15) * (RS*4) + (uint32_t)((lane >> 4) & 1) * 16;
    uint32_t offB = (uint32_t)((lane & 7) + ((lane >> 4) & 1) * 8) * (RS*4)
                  + (uint32_t)((lane >> 3) & 1) * 16;

    float acc[4][4][4];
    #pragma unroll
    for (int i = 0; i < 4; i++)
        #pragma unroll
        for (int j = 0; j < 4; j++)
            #pragma unroll
            for (int e = 0; e < 4; e++) acc[i][j][e] = 0.f;

    uint4 rA0, rA1, rB0, rB1;
    #define GLOAD(c) do { \
        size_t o0_ = (size_t)lr*CDP + (size_t)(c)*8 + kp; \
        size_t o1_ = (size_t)(lr+64)*CDP + (size_t)(c)*8 + kp; \
        rA0 = *(const uint4*)(Ag + o0_); rA1 = *(const uint4*)(Ag + o1_); \
        rB0 = *(const uint4*)(Bg + o0_); rB1 = *(const uint4*)(Bg + o1_); \
    } while (0)
    #define GSTAGE(bi) do { \
        *(uint2*)&Ah[bi][lr][kp]    = make_uint2(rA0.x, rA0.z); \
        *(uint2*)&Al[bi][lr][kp]    = make_uint2(rA0.y, rA0.w); \
        *(uint2*)&Ah[bi][lr+64][kp] = make_uint2(rA1.x, rA1.z); \
        *(uint2*)&Al[bi][lr+64][kp] = make_uint2(rA1.y, rA1.w); \
        *(uint2*)&Bh[bi][lr][kp]    = make_uint2(rB0.x, rB0.z); \
        *(uint2*)&Bl[bi][lr][kp]    = make_uint2(rB0.y, rB0.w); \
        *(uint2*)&Bh[bi][lr+64][kp] = make_uint2(rB1.x, rB1.z); \
        *(uint2*)&Bl[bi][lr+64][kp] = make_uint2(rB1.y, rB1.w); \
    } while (0)

    const int NC = CD / 16;    // 32
    GLOAD(0); GSTAGE(0); GLOAD(1);
    __syncthreads();

    for (int c = 0; c < NC; c++) {
        uint32_t cb = (uint32_t)(c & 1) * BUF;
        uint32_t bh[4][2], bl[4][2];
        #pragma unroll
        for (int ntp = 0; ntp < 2; ntp++) {
            uint32_t nbase = (uint32_t)(wn*32 + ntp*16) * (RS*4);
            ldsm4(bh[2*ntp][0], bh[2*ntp][1], bh[2*ntp+1][0], bh[2*ntp+1][1], aBh + cb + nbase + offB);
            ldsm4(bl[2*ntp][0], bl[2*ntp][1], bl[2*ntp+1][0], bl[2*ntp+1][1], aBl + cb + nbase + offB);
        }
        #pragma unroll
        for (int mt = 0; mt < 4; mt++) {
            uint32_t rbase = (uint32_t)(wm*64 + mt*16) * (RS*4);
            uint32_t ah0, ah1, ah2, ah3, al0, al1, al2, al3;
            ldsm4(ah0, ah1, ah2, ah3, aAh + cb + rbase + offA);
            ldsm4(al0, al1, al2, al3, aAl + cb + rbase + offA);
            #pragma unroll
            for (int nt = 0; nt < 4; nt++) {
                mma16(acc[mt][nt][0], acc[mt][nt][1], acc[mt][nt][2], acc[mt][nt][3],
                      ah0, ah1, ah2, ah3, bh[nt][0], bh[nt][1]);
                mma16(acc[mt][nt][0], acc[mt][nt][1], acc[mt][nt][2], acc[mt][nt][3],
                      ah0, ah1, ah2, ah3, bl[nt][0], bl[nt][1]);
                mma16(acc[mt][nt][0], acc[mt][nt][1], acc[mt][nt][2], acc[mt][nt][3],
                      al0, al1, al2, al3, bh[nt][0], bh[nt][1]);
            }
        }
        if (c + 1 < NC) {
            GSTAGE((c+1) & 1);
            if (c + 2 < NC) GLOAD(c+2);
        }
        __syncthreads();
    }
    #undef GLOAD
    #undef GSTAGE

    if (mode <= 1) {
        uint2* O = (mode == 0) ? g_qp : g_kp;
        #pragma unroll
        for (int mt = 0; mt < 4; mt++) {
            int r = m0 + wm*64 + mt*16 + qr;
            #pragma unroll
            for (int nt = 0; nt < 4; nt++) {
                int colp = (n0 >> 1) + wn*16 + nt*4 + qc;
                uint2 pk;
                split2(acc[mt][nt][0]*scale, acc[mt][nt][1]*scale, pk.x, pk.y);
                O[(size_t)r*CDP + colp] = pk;
                split2(acc[mt][nt][2]*scale, acc[mt][nt][3]*scale, pk.x, pk.y);
                O[(size_t)(r+8)*CDP + colp] = pk;
            }
        }
    } else {
        float* O = (mode == 2) ? g_v : g_gate;
        #pragma unroll
        for (int mt = 0; mt < 4; mt++) {
            int r = m0 + wm*64 + mt*16 + qr;
            #pragma unroll
            for (int nt = 0; nt < 4; nt++) {
                int col = n0 + wn*32 + nt*8 + qc*2;
                float o0 = acc[mt][nt][0], o1 = acc[mt][nt][1];
                float o2 = acc[mt][nt][2], o3 = acc[mt][nt][3];
                if (mode == 3) {
                    float b0 = bg[col], b1 = bg[col+1];
                    o0 = 1.0f/(1.0f + __expf(-(o0+b0)));
                    o1 = 1.0f/(1.0f + __expf(-(o1+b1)));
                    o2 = 1.0f/(1.0f + __expf(-(o2+b0)));
                    o3 = 1.0f/(1.0f + __expf(-(o3+b1)));
                }
                *(float2*)(O + (size_t)r*CD + col)     = make_float2(o0, o1);
                *(float2*)(O + (size_t)(r+8)*CD + col) = make_float2(o2, o3);
            }
        }
    }
}

// ---------------- scores + stats (packed q/k in, fp16 exp out) --------------
__global__ __launch_bounds__(256, 2)
void scores_stats()
{
    __shared__ uint32_t Ah[2][128][RS], Al[2][128][RS];
    __shared__ uint32_t Bh[2][128][RS], Bl[2][128][RS];
    int z = blockIdx.z, b = z >> 3, h = z & 7;
    int m0 = blockIdx.y * 128, n0 = blockIdx.x * 128;
    int tid = threadIdx.x, wid = tid >> 5, lane = tid & 31;
    int wm = wid & 1, wn = wid >> 1;
    int lr = tid >> 2, kp = (tid & 3) * 2;
    int qr = lane >> 2, qc = lane & 3;

    const uint2* Ag = g_qp + (size_t)(b*CS + m0)*CDP + h*32;
    const uint2* Bg = g_kp + (size_t)(b*CS + n0)*CDP + h*32;

    const uint32_t BUF = 128*RS*4;
    uint32_t aAh = s2u(Ah), aAl = s2u(Al), aBh = s2u(Bh), aBl = s2u(Bl);
    uint32_t offA = (uint32_t)(lane & 15) * (RS*4) + (uint32_t)((lane >> 4) & 1) * 16;
    uint32_t offB = (uint32_t)((lane & 7) + ((lane >> 4) & 1) * 8) * (RS*4)
                  + (uint32_t)((lane >> 3) & 1) * 16;

    float acc[4][4][4];
    #pragma unroll
    for (int i = 0; i < 4; i++)
        #pragma unroll
        for (int j = 0; j < 4; j++)
            #pragma unroll
            for (int e = 0; e < 4; e++) acc[i][j][e] = 0.f;

    uint4 rA0, rA1, rB0, rB1;
    #define SLOAD(c) do { \
        size_t o0_ = (size_t)lr*CDP + (size_t)(c)*8 + kp; \
        size_t o1_ = (size_t)(lr+64)*CDP + (size_t)(c)*8 + kp; \
        rA0 = *(const uint4*)(Ag + o0_); rA1 = *(const uint4*)(Ag + o1_); \
        rB0 = *(const uint4*)(Bg + o0_); rB1 = *(const uint4*)(Bg + o1_); \
    } while (0)
    #define SSTAGE(bi) do { \
        *(uint2*)&Ah[bi][lr][kp]    = make_uint2(rA0.x, rA0.z); \
        *(uint2*)&Al[bi][lr][kp]    = make_uint2(rA0.y, rA0.w); \
        *(uint2*)&Ah[bi][lr+64][kp] = make_uint2(rA1.x, rA1.z); \
        *(uint2*)&Al[bi][lr+64][kp] = make_uint2(rA1.y, rA1.w); \
        *(uint2*)&Bh[bi][lr][kp]    = make_uint2(rB0.x, rB0.z); \
        *(uint2*)&Bl[bi][lr][kp]    = make_uint2(rB0.y, rB0.w); \
        *(uint2*)&Bh[bi][lr+64][kp] = make_uint2(rB1.x, rB1.z); \
        *(uint2*)&Bl[bi][lr+64][kp] = make_uint2(rB1.y, rB1.w); \
    } while (0)

    const int NC = CDK / 16;   // 4
    SLOAD(0); SSTAGE(0); SLOAD(1);
    __syncthreads();

    for (int c = 0; c < NC; c++) {
        uint32_t cb = (uint32_t)(c & 1) * BUF;
        uint32_t bh[4][2], bl[4][2];
        #pragma unroll
        for (int ntp = 0; ntp < 2; ntp++) {
            uint32_t nbase = (uint32_t)(wn*32 + ntp*16) * (RS*4);
            ldsm4(bh[2*ntp][0], bh[2*ntp][1], bh[2*ntp+1][0], bh[2*ntp+1][1], aBh + cb + nbase + offB);
            ldsm4(bl[2*ntp][0], bl[2*ntp][1], bl[2*ntp+1][0], bl[2*ntp+1][1], aBl + cb + nbase + offB);
        }
        #pragma unroll
        for (int mt = 0; mt < 4; mt++) {
            uint32_t rbase = (uint32_t)(wm*64 + mt*16) * (RS*4);
            uint32_t ah0, ah1, ah2, ah3, al0, al1, al2, al3;
            ldsm4(ah0, ah1, ah2, ah3, aAh + cb + rbase + offA);
            ldsm4(al0, al1, al2, al3, aAl + cb + rbase + offA);
            #pragma unroll
            for (int nt = 0; nt < 4; nt++) {
                mma16(acc[mt][nt][0], acc[mt][nt][1], acc[mt][nt][2], acc[mt][nt][3],
                      ah0, ah1, ah2, ah3, bh[nt][0], bh[nt][1]);
                mma16(acc[mt][nt][0], acc[mt][nt][1], acc[mt][nt][2], acc[mt][nt][3],
                      ah0, ah1, ah2, ah3, bl[nt][0], bl[nt][1]);
                mma16(acc[mt][nt][0], acc[mt][nt][1], acc[mt][nt][2], acc[mt][nt][3],
                      al0, al1, al2, al3, bh[nt][0], bh[nt][1]);
            }
        }
        if (c + 1 < NC) {
            SSTAGE((c+1) & 1);
            if (c + 2 < NC) SLOAD(c+2);
        }
        __syncthreads();
    }
    #undef SLOAD
    #undef SSTAGE

    // epilogue: ex = exp(x); stats partials; store fp16(ex^2 * 2^-8)
    float csl[4][2];
    #pragma unroll
    for (int nt = 0; nt < 4; nt++) { csl[nt][0] = 0.f; csl[nt][1] = 0.f; }
    #pragma unroll
    for (int mt = 0; mt < 4; mt++) {
        float ex[4][4];
        #pragma unroll
        for (int nt = 0; nt < 4; nt++)
            #pragma unroll
            for (int e = 0; e < 4; e++) ex[nt][e] = fast_exp(acc[mt][nt][e]);
        float r0 = 0.f, r1 = 0.f;
        #pragma unroll
        for (int nt = 0; nt < 4; nt++) {
            r0 += ex[nt][0] + ex[nt][1];
            r1 += ex[nt][2] + ex[nt][3];
            csl[nt][0] += ex[nt][0] + ex[nt][2];
            csl[nt][1] += ex[nt][1] + ex[nt][3];
        }
        r0 += __shfl_xor_sync(0xffffffffu, r0, 1);
        r0 += __shfl_xor_sync(0xffffffffu, r0, 2);
        r1 += __shfl_xor_sync(0xffffffffu, r1, 1);
        r1 += __shfl_xor_sync(0xffffffffu, r1, 2);
        int row0 = m0 + wm*64 + mt*16 + qr;
        if (qc == 0) {
            int rslot = blockIdx.x * 4 + wn;
            g_rpart[((size_t)(z*CS + row0) << 6) + rslot]     = r0;
            g_rpart[((size_t)(z*CS + row0 + 8) << 6) + rslot] = r1;
        }
        #pragma unroll
        for (int nt = 0; nt < 4; nt++) {
            int colp = (n0 >> 1) + wn*16 + nt*4 + qc;
            g_p[(size_t)(z*CS + row0)*CSP + colp] =
                pack_h2(ex[nt][0]*ex[nt][0]*PSCALE, ex[nt][1]*ex[nt][1]*PSCALE);
            g_p[(size_t)(z*CS + row0 + 8)*CSP + colp] =
                pack_h2(ex[nt][2]*ex[nt][2]*PSCALE, ex[nt][3]*ex[nt][3]*PSCALE);
        }
    }
    #pragma unroll
    for (int nt = 0; nt < 4; nt++) {
        #pragma unroll
        for (int j = 0; j < 2; j++) {
            float v = csl[nt][j];
            v += __shfl_xor_sync(0xffffffffu, v, 4);
            v += __shfl_xor_sync(0xffffffffu, v, 8);
            v += __shfl_xor_sync(0xffffffffu, v, 16);
            if (qr == 0) {
                int cslot = blockIdx.y * 2 + wm;
                int col = n0 + wn*32 + nt*8 + qc*2 + j;
                g_cpart[((size_t)(z*CS + col) << 5) + cslot] = v;
            }
        }
    }
}

// ---------------- finalize: reduce partials -> reciprocals ------------------
__global__ __launch_bounds__(256)
void finalize_kernel()
{
    int i = blockIdx.x * 256 + threadIdx.x;
    if (i < CBH*CS) {
        const float4* p = (const float4*)(g_rpart + ((size_t)i << 6));
        float s = 0.f;
        #pragma unroll
        for (int j = 0; j < 16; j++) {
            float4 v = p[j];
            s += v.x + v.y + v.z + v.w;
        }
        g_rsum[i] = 1.0f / s;
    } else {
        i -= CBH*CS;
        const float4* p = (const float4*)(g_cpart + ((size_t)i << 5));
        float s = 0.f;
        #pragma unroll
        for (int j = 0; j < 8; j++) {
            float4 v = p[j];
            s += v.x + v.y + v.z + v.w;
        }
        g_csum[i] = 1.0f / s;
    }
}

// ---------------- V transpose: ci*256 folded, fp16 split packed -------------
__global__ __launch_bounds__(256)
void vtrans_ci()
{
    __shared__ float tile[64][65];
    int z = blockIdx.y, b = z >> 3, h = z & 7;
    int t0 = blockIdx.x * 64;
    const float* src = g_v + (size_t)b*CS*CD + h*CDK;
    int tid = threadIdx.x;
    #pragma unroll
    for (int i = 0; i < 16; i++) {
        int idx = tid + i*256;
        int tr = idx >> 6, d = idx & 63;
        tile[tr][d] = src[(size_t)(t0 + tr)*CD + d] * (g_csum[z*CS + t0 + tr] * VSCALE);
    }
    __syncthreads();
    #pragma unroll
    for (int i = 0; i < 8; i++) {
        int idx = tid + i*256;
        int d = idx >> 5, tp = idx & 31;
        uint2 pk;
        splith2(tile[2*tp][d], tile[2*tp+1][d], pk.x, pk.y);
        g_vtp[((size_t)z*CDK + d)*CSP + (t0 >> 1) + tp] = pk;
    }
}

// ---------------- PV: fp16 P (single) x fp16 V (split), packed out ----------
__global__ __launch_bounds__(256)
void pv_kernel()
{
    __shared__ uint32_t Ph[2][128][RS];
    __shared__ uint32_t Vh[2][64][RS], Vl[2][64][RS];
    int z = blockIdx.y, b = z >> 3, h = z & 7;
    int s0 = blockIdx.x * 128;
    int tid = threadIdx.x, wid = tid >> 5, lane = tid & 31;
    int wm = wid & 3, wn = wid >> 2;
    int qr = lane >> 2, qc = lane & 3;

    int pr = tid >> 1;                 // P row 0..127
    int pp = (tid & 1) * 4;            // uint32 base 0/4 within 8-u32 chunk row
    int vr = tid >> 2;                 // V^T row (dk) 0..63
    int vp = (tid & 3) * 2;            // pair base 0,2,4,6
    const uint32_t* aph = g_p   + (size_t)(z*CS + s0 + pr)*CSP;
    const uint2*    avh = g_vtp + ((size_t)z*CDK + vr)*CSP;

    const uint32_t BUFP = 128*RS*4, BUFV = 64*RS*4;
    uint32_t aPh = s2u(Ph), aVh = s2u(Vh), aVl = s2u(Vl);
    uint32_t offA = (uint32_t)(lane & 15) * (RS*4) + (uint32_t)((lane >> 4) & 1) * 16;
    uint32_t offB = (uint32_t)((lane & 7) + ((lane >> 4) & 1) * 8) * (RS*4)
                  + (uint32_t)((lane >> 3) & 1) * 16;

    float acc[2][4][4];
    #pragma unroll
    for (int i = 0; i < 2; i++)
        #pragma unroll
        for (int j = 0; j < 4; j++)
            #pragma unroll
            for (int e = 0; e < 4; e++) acc[i][j][e] = 0.f;

    uint4 rp0, rv0;
    #define PLOAD(c) do { \
        rp0 = *(const uint4*)(aph + (size_t)(c)*8 + pp); \
        rv0 = *(const uint4*)(avh + (size_t)(c)*8 + vp); \
    } while (0)
    #define PSTAGE(bi) do { \
        *(uint4*)&Ph[bi][pr][pp] = rp0; \
        *(uint2*)&Vh[bi][vr][vp] = make_uint2(rv0.x, rv0.z); \
        *(uint2*)&Vl[bi][vr][vp] = make_uint2(rv0.y, rv0.w); \
    } while (0)

    const int NC = CS / 16;            // 128 chunks
    PLOAD(0); PSTAGE(0); PLOAD(1);
    __syncthreads();

    for (int c = 0; c < NC; c++) {
        uint32_t cbP = (uint32_t)(c & 1) * BUFP;
        uint32_t cbV = (uint32_t)(c & 1) * BUFV;
        uint32_t bh[4][2], bl[4][2];
        #pragma unroll
        for (int ntp = 0; ntp < 2; ntp++) {
            uint32_t nbase = (uint32_t)(wn*32 + ntp*16) * (RS*4);
            ldsm4(bh[2*ntp][0], bh[2*ntp][1], bh[2*ntp+1][0], bh[2*ntp+1][1], aVh + cbV + nbase + offB);
            ldsm4(bl[2*ntp][0], bl[2*ntp][1], bl[2*ntp+1][0], bl[2*ntp+1][1], aVl + cbV + nbase + offB);
        }
        #pragma unroll
        for (int mt = 0; mt < 2; mt++) {
            uint32_t rbase = (uint32_t)(wm*32 + mt*16) * (RS*4);
            uint32_t a0, a1, a2, a3;
            ldsm4(a0, a1, a2, a3, aPh + cbP + rbase + offA);
            #pragma unroll
            for (int nt = 0; nt < 4; nt++) {
                mma16h(acc[mt][nt][0], acc[mt][nt][1], acc[mt][nt][2], acc[mt][nt][3],
                       a0, a1, a2, a3, bh[nt][0], bh[nt][1]);
                mma16h(acc[mt][nt][0], acc[mt][nt][1], acc[mt][nt][2], acc[mt][nt][3],
                       a0, a1, a2, a3, bl[nt][0], bl[nt][1]);
            }
        }
        if (c + 1 < NC) {
            PSTAGE((c+1) & 1);
            if (c + 2 < NC) PLOAD(c+2);
        }
        __syncthreads();
    }
    #undef PLOAD
    #undef PSTAGE
    // epilogue: * rsum_inv, * gate -> g_aop (packed bf16 split)
    #pragma unroll
    for (int mt = 0; mt < 2; mt++) {
        #pragma unroll
        for (int half = 0; half < 2; half++) {
            int srow = s0 + wm*32 + mt*16 + qr + half*8;
            float ri = g_rsum[(size_t)z*CS + srow];
            const float* grow = g_gate + ((size_t)b*CS + srow)*CD + h*CDK;
            uint2* orow       = g_aop  + ((size_t)b*CS + srow)*CDP + h*32;
            #pragma unroll
            for (int nt = 0; nt < 4; nt++) {
                int col = wn*32 + nt*8 + qc*2;
                float2 gg = *(const float2*)(grow + col);
                float o0 = acc[mt][nt][half*2+0] * ri * gg.x;
                float o1 = acc[mt][nt][half*2+1] * ri * gg.y;
                uint2 pk;
                split2(o0, o1, pk.x, pk.y);
                orow[col >> 1] = pk;
            }
        }
    }
}

// ---------------- output projection: packed A/B, bias -> d_out --------------
__global__ __launch_bounds__(256, 2)
void out_gemm(const float* __restrict__ bo, float* __restrict__ C)
{
    __shared__ uint32_t Ah[2][128][RS], Al[2][128][RS];
    __shared__ uint32_t Bh[2][128][RS], Bl[2][128][RS];
    int tid = threadIdx.x, wid = tid >> 5, lane = tid & 31;
    int wm = wid & 1, wn = wid >> 1;
    int m0 = blockIdx.y * 128, n0 = blockIdx.x * 128;
    const uint2* Ag = g_aop + (size_t)m0 * CDP;
    const uint2* Bg = g_wp[4] + (size_t)n0 * CDP;
    int lr = tid >> 2, kp = (tid & 3) * 2;
    int qr = lane >> 2, qc = lane & 3;

    const uint32_t BUF = 128*RS*4;
    uint32_t aAh = s2u(Ah), aAl = s2u(Al), aBh = s2u(Bh), aBl = s2u(Bl);
    uint32_t offA = (uint32_t)(lane & 15) * (RS*4) + (uint32_t)((lane >> 4) & 1) * 16;
    uint32_t offB = (uint32_t)((lane & 7) + ((lane >> 4) & 1) * 8) * (RS*4)
                  + (uint32_t)((lane >> 3) & 1) * 16;

    float acc[4][4][4];
    #pragma unroll
    for (int i = 0; i < 4; i++)
        #pragma unroll
        for (int j = 0; j < 4; j++)
            #pragma unroll
            for (int e = 0; e < 4; e++) acc[i][j][e] = 0.f;

    uint4 rA0, rA1, rB0, rB1;
    #define OLOAD(c) do { \
        size_t o0_ = (size_t)lr*CDP + (size_t)(c)*8 + kp; \
        size_t o1_ = (size_t)(lr+64)*CDP + (size_t)(c)*8 + kp; \
        rA0 = *(const uint4*)(Ag + o0_); rA1 = *(const uint4*)(Ag + o1_); \
        rB0 = *(const uint4*)(Bg + o0_); rB1 = *(const uint4*)(Bg + o1_); \
    } while (0)
    #define OSTAGE(bi) do { \
        *(uint2*)&Ah[bi][lr][kp]    = make_uint2(rA0.x, rA0.z); \
        *(uint2*)&Al[bi][lr][kp]    = make_uint2(rA0.y, rA0.w); \
        *(uint2*)&Ah[bi][lr+64][kp] = make_uint2(rA1.x, rA1.z); \
        *(uint2*)&Al[bi][lr+64][kp] = make_uint2(rA1.y, rA1.w); \
        *(uint2*)&Bh[bi][lr][kp]    = make_uint2(rB0.x, rB0.z); \
        *(uint2*)&Bl[bi][lr][kp]    = make_uint2(rB0.y, rB0.w); \
        *(uint2*)&Bh[bi][lr+64][kp] = make_uint2(rB1.x, rB1.z); \
        *(uint2*)&Bl[bi][lr+64][kp] = make_uint2(rB1.y, rB1.w); \
    } while (0)

    const int NC = CD / 16;
    OLOAD(0); OSTAGE(0); OLOAD(1);
    __syncthreads();

    for (int c = 0; c < NC; c++) {
        uint32_t cb = (uint32_t)(c & 1) * BUF;
        uint32_t bh[4][2], bl[4][2];
        #pragma unroll
        for (int ntp = 0; ntp < 2; ntp++) {
            uint32_t nbase = (uint32_t)(wn*32 + ntp*16) * (RS*4);
            ldsm4(bh[2*ntp][0], bh[2*ntp][1], bh[2*ntp+1][0], bh[2*ntp+1][1], aBh + cb + nbase + offB);
            ldsm4(bl[2*ntp][0], bl[2*ntp][1], bl[2*ntp+1][0], bl[2*ntp+1][1], aBl + cb + nbase + offB);
        }
        #pragma unroll
        for (int mt = 0; mt < 4; mt++) {
            uint32_t rbase = (uint32_t)(wm*64 + mt*16) * (RS*4);
            uint32_t ah0, ah1, ah2, ah3, al0, al1, al2, al3;
            ldsm4(ah0, ah1, ah2, ah3, aAh + cb + rbase + offA);
            ldsm4(al0, al1, al2, al3, aAl + cb + rbase + offA);
            #pragma unroll
            for (int nt = 0; nt < 4; nt++) {
                mma16(acc[mt][nt][0], acc[mt][nt][1], acc[mt][nt][2], acc[mt][nt][3],
                      ah0, ah1, ah2, ah3, bh[nt][0], bh[nt][1]);
                mma16(acc[mt][nt][0], acc[mt][nt][1], acc[mt][nt][2], acc[mt][nt][3],
                      ah0, ah1, ah2, ah3, bl[nt][0], bl[nt][1]);
                mma16(acc[mt][nt][0], acc[mt][nt][1], acc[mt][nt][2], acc[mt][nt][3],
                      al0, al1, al2, al3, bh[nt][0], bh[nt][1]);
            }
        }
        if (c + 1 < NC) {
            OSTAGE((c+1) & 1);
            if (c + 2 < NC) OLOAD(c+2);
        }
        __syncthreads();
    }
    #undef OLOAD
    #undef OSTAGE
    #pragma unroll
    for (int mt = 0; mt < 4; mt++) {
        int r = m0 + wm*64 + mt*16 + qr;
        #pragma unroll
        for (int nt = 0; nt < 4; nt++) {
            int col = n0 + wn*32 + nt*8 + qc*2;
            float b0 = bo[col], b1 = bo[col+1];
            *(float2*)(C + (size_t)r*CD + col) =
                make_float2(acc[mt][nt][0] + b0, acc[mt][nt][1] + b1);
            *(float2*)(C + (size_t)(r+8)*CD + col) =
                make_float2(acc[mt][nt][2] + b0, acc[mt][nt][3] + b1);
        }
    }
}

// ---------------- launch ----------------
extern "C" void kernel_launch(void* const* d_in, const int* in_sizes, int n_in,
                              void* d_out, int out_size)
{
    const float* x_q   = (const float*)d_in[0];
    const float* x_k   = (const float*)d_in[1];
    const float* Wq    = (const float*)d_in[2];
    const float* Wk    = (const float*)d_in[3];
    const float* Wv    = (const float*)d_in[4];
    const float* Wg    = (const float*)d_in[5];
    const float* bg    = (const float*)d_in[6];
    const float* Wo    = (const float*)d_in[7];
    const float* bo    = (const float*)d_in[8];
    const float* gamma = (const float*)d_in[9];
    const float* beta  = (const float*)d_in[10];
    float* out = (float*)d_out;

    // 1. LayerNorm (packed-split output) + weight split
    ln_kernel<<<2*CM, 256>>>(x_q, x_k, gamma, beta);
    wsplit_kernel<<<dim3(CD*CDP/256, 5), 256>>>(Wq, Wk, Wv, Wg, Wo);

    // 2. All projections, one launch (copy-staged)
    proj_all<<<dim3(CD/128, CM/128, 4), 256>>>(bg);

    // 3. Scores + stats, store fp16 exp(2x)*2^-8 (half traffic)
    scores_stats<<<dim3(CS/128, CS/128, CBH), 256>>>();

    // 4. Reduce partials -> reciprocal sums
    finalize_kernel<<<(2*CBH*CS)/256, 256>>>();

    // 5. V transpose with ci*256 folded, fp16 split
    vtrans_ci<<<dim3(CS/64, CBH), 256>>>();

    // 6. PV: fp16 MMA (2 per tile), packed bf16 split out
    pv_kernel<<<dim3(CS/128, CBH), 256>>>();

    // 7. Output projection (copy-staged) + bias -> d_out
    out_gemm<<<dim3(CD/128, CM/128), 256>>>(bo, out);
}